// round 8
// baseline (speedup 1.0000x reference)
#include <cuda_runtime.h>
#include <math.h>
#include <stdint.h>

// Problem constants
#define BB   32
#define SS   512
#define DD   512
#define HH   8
#define DKK  64
#define FFD  2048
#define NBLK 2
#define MTOK (BB*SS)            // 16384 token rows
#define BSD  (BB*SS*DD)         // 8388608
#define BSF  (BB*SS*FFD)        // 33554432

// Scratch (static device globals — no allocation allowed)
__device__ float g_x[BSD];
__device__ float g_y[BSD];
__device__ float g_xr[BSD];
__device__ float g_yr[BSD];
__device__ float g_q[BSD];
__device__ float g_v[BSD];
__device__ float g_t[BSD];
__device__ float g_ff[BSF];
__device__ float g_wk[NBLK*DD*DD];
__device__ float g_wv[NBLK*DD*DD];
__device__ float g_wo[NBLK*DD*DD];
__device__ float g_w1[NBLK*DD*FFD];
__device__ float g_w2[NBLK*FFD*DD];

// ---------------------------------------------------------------------------
// helpers
// ---------------------------------------------------------------------------
__device__ __forceinline__ uint32_t to_tf32(float x) {
    uint32_t y;
    asm("cvt.rna.tf32.f32 %0, %1;" : "=r"(y) : "f"(x));
    return y;
}
__device__ __forceinline__ float rtf(float x) {
    return __uint_as_float(to_tf32(x));
}
__device__ __forceinline__ void mma_tf32(float c[4],
                                         uint32_t a0, uint32_t a1,
                                         uint32_t a2, uint32_t a3,
                                         uint32_t b0, uint32_t b1)
{
    asm volatile(
        "mma.sync.aligned.m16n8k8.row.col.f32.tf32.tf32.f32 "
        "{%0,%1,%2,%3}, {%4,%5,%6,%7}, {%8,%9}, {%0,%1,%2,%3};"
        : "+f"(c[0]), "+f"(c[1]), "+f"(c[2]), "+f"(c[3])
        : "r"(a0), "r"(a1), "r"(a2), "r"(a3), "r"(b0), "r"(b1));
}
__device__ __forceinline__ void cp_async16(uint32_t smem_addr, const void* gptr) {
    asm volatile("cp.async.cg.shared.global [%0], [%1], 16;"
                 :: "r"(smem_addr), "l"(gptr));
}
__device__ __forceinline__ void cp_commit() {
    asm volatile("cp.async.commit_group;");
}
template<int N>
__device__ __forceinline__ void cp_wait() {
    asm volatile("cp.async.wait_group %0;" :: "n"(N));
}

// ---------------------------------------------------------------------------
// round-copy: out = tf32_rna(in)   (n4 = element count / 4)
// ---------------------------------------------------------------------------
__global__ void round_tf32_kernel(const float4* __restrict__ in,
                                  float4* __restrict__ out, int n4)
{
    int i = blockIdx.x * blockDim.x + threadIdx.x;
    if (i >= n4) return;
    float4 v = in[i];
    v.x = rtf(v.x); v.y = rtf(v.y); v.z = rtf(v.z); v.w = rtf(v.w);
    out[i] = v;
}

// ---------------------------------------------------------------------------
// x = qe+pe, y = qa+pe (full fp32) + tf32-rounded copies xr, yr
// ---------------------------------------------------------------------------
__global__ void add_pe_kernel(const float4* __restrict__ qe,
                              const float4* __restrict__ qa,
                              const float4* __restrict__ pe,
                              float4* __restrict__ x,  float4* __restrict__ y,
                              float4* __restrict__ xr, float4* __restrict__ yr)
{
    int i = blockIdx.x * blockDim.x + threadIdx.x;
    const int n4 = BSD / 4;
    if (i >= n4) return;
    int pi = i & (SS * DD / 4 - 1);
    float4 p = pe[pi];
    float4 a = qe[i];
    a.x += p.x; a.y += p.y; a.z += p.z; a.w += p.w;
    x[i] = a;
    xr[i] = make_float4(rtf(a.x), rtf(a.y), rtf(a.z), rtf(a.w));
    float4 b = qa[i];
    b.x += p.x; b.y += p.y; b.z += p.z; b.w += p.w;
    y[i] = b;
    yr[i] = make_float4(rtf(b.x), rtf(b.y), rtf(b.z), rtf(b.w));
}

// ---------------------------------------------------------------------------
// Pipelined TF32 GEMM v2: C[M,N] = A[M,K] @ W[K,N] + bias[N]
// CTA 128x128, BK=32, 128 threads = 4 warps (2x2), 64x64 warp tiles.
// 2-stage cp.async double buffer. Operands are pre-rounded tf32 fp32 bits.
// MODE 0: plain fp32 out. MODE 1: ReLU then tf32-round out.
// As: [2][128][36]  (frag addr 4*grp+tig mod 32 -> conflict-free)
// Bs: [2][32][136]  (frag addr 8*tig+grp mod 32 -> conflict-free)
// ---------------------------------------------------------------------------
#define AST 36
#define BST 136
#define ASZ (128 * AST)
#define BSZ (32 * BST)
#define GEMM_SMEM ((2 * ASZ + 2 * BSZ) * sizeof(float))

template<int MODE>
__global__ void __launch_bounds__(128, 2) tf32_gemm_v2(
    const float* __restrict__ A, const float* __restrict__ W,
    const float* __restrict__ bias, float* __restrict__ C,
    int M, int N, int K)
{
    extern __shared__ float smf[];
    float* Asm = smf;                 // [2][128][AST]
    float* Bsm = smf + 2 * ASZ;       // [2][32][BST]

    const int tid  = threadIdx.x;
    const int lane = tid & 31;
    const int wid  = tid >> 5;
    const int wm   = wid & 1;          // 0..1
    const int wn   = wid >> 1;         // 0..1
    const int grp  = lane >> 2;
    const int tig  = lane & 3;
    const int m0   = blockIdx.y * 128;
    const int n0   = blockIdx.x * 128;

    const uint32_t sA = (uint32_t)__cvta_generic_to_shared(Asm);
    const uint32_t sB = (uint32_t)__cvta_generic_to_shared(Bsm);

    const int a_row = tid;             // 0..127, loads 32 floats (8 chunks)
    const int b_row = tid >> 2;        // 0..31
    const int b_c0  = (tid & 3) * 32;  // float col base, 32 floats (8 chunks)

    float acc[4][8][4];
#pragma unroll
    for (int i = 0; i < 4; i++)
#pragma unroll
        for (int j = 0; j < 8; j++)
#pragma unroll
            for (int r = 0; r < 4; r++) acc[i][j][r] = 0.f;

    const int nk = K >> 5;

    auto load_stage = [&](int stg, int k0) {
        const float* ga = A + (size_t)(m0 + a_row) * K + k0;
        uint32_t da = sA + (uint32_t)((stg * ASZ + a_row * AST) * 4);
#pragma unroll
        for (int c = 0; c < 8; c++) cp_async16(da + c * 16, ga + c * 4);
        const float* gb = W + (size_t)(k0 + b_row) * N + n0 + b_c0;
        uint32_t db = sB + (uint32_t)((stg * BSZ + b_row * BST + b_c0) * 4);
#pragma unroll
        for (int c = 0; c < 8; c++) cp_async16(db + c * 16, gb + c * 4);
    };

    load_stage(0, 0);
    cp_commit();

    for (int kt = 0; kt < nk; kt++) {
        if (kt + 1 < nk) load_stage((kt + 1) & 1, (kt + 1) * 32);
        cp_commit();
        cp_wait<1>();
        __syncthreads();

        const float* pA = Asm + (kt & 1) * ASZ;
        const float* pB = Bsm + (kt & 1) * BSZ;

#pragma unroll
        for (int kk = 0; kk < 32; kk += 8) {
            uint32_t af[4][4];
            uint32_t bf[8][2];
#pragma unroll
            for (int mt = 0; mt < 4; mt++) {
                int mr = wm * 64 + mt * 16 + grp;
                af[mt][0] = __float_as_uint(pA[(mr    ) * AST + kk + tig    ]);
                af[mt][1] = __float_as_uint(pA[(mr + 8) * AST + kk + tig    ]);
                af[mt][2] = __float_as_uint(pA[(mr    ) * AST + kk + tig + 4]);
                af[mt][3] = __float_as_uint(pA[(mr + 8) * AST + kk + tig + 4]);
            }
#pragma unroll
            for (int nt = 0; nt < 8; nt++) {
                int nc = wn * 64 + nt * 8 + grp;
                bf[nt][0] = __float_as_uint(pB[(kk + tig    ) * BST + nc]);
                bf[nt][1] = __float_as_uint(pB[(kk + tig + 4) * BST + nc]);
            }
#pragma unroll
            for (int mt = 0; mt < 4; mt++)
#pragma unroll
                for (int nt = 0; nt < 8; nt++)
                    mma_tf32(acc[mt][nt],
                             af[mt][0], af[mt][1], af[mt][2], af[mt][3],
                             bf[nt][0], bf[nt][1]);
        }
        __syncthreads();
    }

    // Epilogue
#pragma unroll
    for (int mt = 0; mt < 4; mt++) {
#pragma unroll
        for (int nt = 0; nt < 8; nt++) {
            int row = m0 + wm * 64 + mt * 16 + grp;
            int col = n0 + wn * 64 + nt * 8 + tig * 2;
            float b0 = bias[col], b1 = bias[col + 1];
            float v0 = acc[mt][nt][0] + b0;
            float v1 = acc[mt][nt][1] + b1;
            float v2 = acc[mt][nt][2] + b0;
            float v3 = acc[mt][nt][3] + b1;
            if (MODE == 1) {
                v0 = rtf(fmaxf(v0, 0.f)); v1 = rtf(fmaxf(v1, 0.f));
                v2 = rtf(fmaxf(v2, 0.f)); v3 = rtf(fmaxf(v3, 0.f));
            }
            *(float2*)(C + (size_t)row * N + col)       = make_float2(v0, v1);
            *(float2*)(C + (size_t)(row + 8) * N + col) = make_float2(v2, v3);
        }
    }
}

// ---------------------------------------------------------------------------
// TF32 tensor-core flash attention (R4 core; output tf32-rounded for Wo GEMM)
// ---------------------------------------------------------------------------
#define QK_PAD 68
#define V_PAD  72
#define ATTN_SMEM ((2 * 64 * QK_PAD + 64 * V_PAD) * sizeof(uint32_t))

__global__ void __launch_bounds__(128, 4) attn_mma_kernel(
    const float* __restrict__ Q, const float* __restrict__ V,
    const float* __restrict__ FR, float* __restrict__ Out)
{
    extern __shared__ uint32_t smu[];
    uint32_t* Qs = smu;
    uint32_t* Ks = smu + 64 * QK_PAD;
    uint32_t* Vs = smu + 2 * 64 * QK_PAD;

    const int qt   = blockIdx.x;
    const int bh   = blockIdx.y;
    const int b    = bh >> 3;
    const int h    = bh & 7;
    const int tid  = threadIdx.x;
    const int lane = tid & 31;
    const int w    = tid >> 5;
    const int grp  = lane >> 2;
    const int tig  = lane & 3;
    const int q0   = qt * 64;
    const size_t base = (size_t)b * SS * DD + (size_t)h * DKK;

#pragma unroll
    for (int j = 0; j < 8; j++) {
        int idx = j * 128 + tid;
        int r   = idx >> 4;
        int c4  = (idx & 15) * 4;
        float4 v = *(const float4*)(Q + base + (size_t)(q0 + r) * DD + c4);
        uint32_t* d = Qs + r * QK_PAD + c4;
        d[0] = to_tf32(v.x); d[1] = to_tf32(v.y);
        d[2] = to_tf32(v.z); d[3] = to_tf32(v.w);
    }

    const int rg0 = q0 + w * 16 + grp;
    const float frs0 = FR[b * SS + rg0]     * 0.125f;
    const float frs1 = FR[b * SS + rg0 + 8] * 0.125f;

    float m0 = -3.0e38f, m1 = -3.0e38f, l0 = 0.f, l1 = 0.f;
    float o[8][4];
#pragma unroll
    for (int nt = 0; nt < 8; nt++)
#pragma unroll
        for (int r = 0; r < 4; r++) o[nt][r] = 0.f;

    for (int kt = 0; kt <= qt; kt++) {
        __syncthreads();
#pragma unroll
        for (int j = 0; j < 8; j++) {
            int idx = j * 128 + tid;
            int r   = idx >> 4;
            int c4  = (idx & 15) * 4;
            float4 kv = *(const float4*)(Q + base + (size_t)(kt * 64 + r) * DD + c4);
            float4 vv = *(const float4*)(V + base + (size_t)(kt * 64 + r) * DD + c4);
            uint32_t* kd = Ks + r * QK_PAD + c4;
            uint32_t* vd = Vs + r * V_PAD  + c4;
            kd[0] = to_tf32(kv.x); kd[1] = to_tf32(kv.y);
            kd[2] = to_tf32(kv.z); kd[3] = to_tf32(kv.w);
            vd[0] = to_tf32(vv.x); vd[1] = to_tf32(vv.y);
            vd[2] = to_tf32(vv.z); vd[3] = to_tf32(vv.w);
        }
        __syncthreads();

        float sc[8][4];
#pragma unroll
        for (int nt = 0; nt < 8; nt++)
#pragma unroll
            for (int r = 0; r < 4; r++) sc[nt][r] = 0.f;

#pragma unroll
        for (int kk = 0; kk < 64; kk += 8) {
            const int mr = w * 16 + grp;
            uint32_t a0 = Qs[(mr    ) * QK_PAD + kk + tig    ];
            uint32_t a1 = Qs[(mr + 8) * QK_PAD + kk + tig    ];
            uint32_t a2 = Qs[(mr    ) * QK_PAD + kk + tig + 4];
            uint32_t a3 = Qs[(mr + 8) * QK_PAD + kk + tig + 4];
#pragma unroll
            for (int nt = 0; nt < 8; nt++) {
                uint32_t b0 = Ks[(nt * 8 + grp) * QK_PAD + kk + tig    ];
                uint32_t b1 = Ks[(nt * 8 + grp) * QK_PAD + kk + tig + 4];
                mma_tf32(sc[nt], a0, a1, a2, a3, b0, b1);
            }
        }

        const bool diag = (kt == qt);
        float mx0 = -3.0e38f, mx1 = -3.0e38f;
#pragma unroll
        for (int nt = 0; nt < 8; nt++) {
            int cg = kt * 64 + nt * 8 + 2 * tig;
            float s0 = sc[nt][0] * frs0;
            float s1 = sc[nt][1] * frs0;
            float s2 = sc[nt][2] * frs1;
            float s3 = sc[nt][3] * frs1;
            if (diag) {
                if (cg     >= rg0)     s0 = -1e30f;
                if (cg + 1 >= rg0)     s1 = -1e30f;
                if (cg     >= rg0 + 8) s2 = -1e30f;
                if (cg + 1 >= rg0 + 8) s3 = -1e30f;
            }
            sc[nt][0] = s0; sc[nt][1] = s1; sc[nt][2] = s2; sc[nt][3] = s3;
            mx0 = fmaxf(mx0, fmaxf(s0, s1));
            mx1 = fmaxf(mx1, fmaxf(s2, s3));
        }
        mx0 = fmaxf(mx0, __shfl_xor_sync(0xffffffffu, mx0, 1));
        mx0 = fmaxf(mx0, __shfl_xor_sync(0xffffffffu, mx0, 2));
        mx1 = fmaxf(mx1, __shfl_xor_sync(0xffffffffu, mx1, 1));
        mx1 = fmaxf(mx1, __shfl_xor_sync(0xffffffffu, mx1, 2));

        float mn0 = fmaxf(m0, mx0);
        float mn1 = fmaxf(m1, mx1);
        float al0 = __expf(m0 - mn0);
        float al1 = __expf(m1 - mn1);
        m0 = mn0; m1 = mn1;

        float su0 = 0.f, su1 = 0.f;
        uint32_t pu[8][4];
#pragma unroll
        for (int nt = 0; nt < 8; nt++) {
            float p0 = __expf(sc[nt][0] - mn0);
            float p1 = __expf(sc[nt][1] - mn0);
            float p2 = __expf(sc[nt][2] - mn1);
            float p3 = __expf(sc[nt][3] - mn1);
            su0 += p0 + p1;
            su1 += p2 + p3;
            pu[nt][0] = to_tf32(p0); pu[nt][1] = to_tf32(p1);
            pu[nt][2] = to_tf32(p2); pu[nt][3] = to_tf32(p3);
        }
        su0 += __shfl_xor_sync(0xffffffffu, su0, 1);
        su0 += __shfl_xor_sync(0xffffffffu, su0, 2);
        su1 += __shfl_xor_sync(0xffffffffu, su1, 1);
        su1 += __shfl_xor_sync(0xffffffffu, su1, 2);
        l0 = l0 * al0 + su0;
        l1 = l1 * al1 + su1;
#pragma unroll
        for (int nt = 0; nt < 8; nt++) {
            o[nt][0] *= al0; o[nt][1] *= al0;
            o[nt][2] *= al1; o[nt][3] *= al1;
        }

        const int srcbase = (lane & ~3) | (tig >> 1);
        const int odd = tig & 1;
#pragma unroll
        for (int j = 0; j < 8; j++) {
            uint32_t x0a = __shfl_sync(0xffffffffu, pu[j][0], srcbase);
            uint32_t x1a = __shfl_sync(0xffffffffu, pu[j][1], srcbase);
            uint32_t x2a = __shfl_sync(0xffffffffu, pu[j][2], srcbase);
            uint32_t x3a = __shfl_sync(0xffffffffu, pu[j][3], srcbase);
            uint32_t x0b = __shfl_sync(0xffffffffu, pu[j][0], srcbase + 2);
            uint32_t x1b = __shfl_sync(0xffffffffu, pu[j][1], srcbase + 2);
            uint32_t x2b = __shfl_sync(0xffffffffu, pu[j][2], srcbase + 2);
            uint32_t x3b = __shfl_sync(0xffffffffu, pu[j][3], srcbase + 2);
            uint32_t a0 = odd ? x1a : x0a;
            uint32_t a1 = odd ? x3a : x2a;
            uint32_t a2 = odd ? x1b : x0b;
            uint32_t a3 = odd ? x3b : x2b;
#pragma unroll
            for (int nt = 0; nt < 8; nt++) {
                uint32_t b0 = Vs[(j * 8 + tig    ) * V_PAD + nt * 8 + grp];
                uint32_t b1 = Vs[(j * 8 + tig + 4) * V_PAD + nt * 8 + grp];
                mma_tf32(o[nt], a0, a1, a2, a3, b0, b1);
            }
        }
    }

    float inv0 = (rg0 == 0) ? 0.f : (1.0f / l0);
    float inv1 = 1.0f / l1;
#pragma unroll
    for (int nt = 0; nt < 8; nt++) {
        int col = nt * 8 + tig * 2;
        *(float2*)(Out + base + (size_t)(rg0    ) * DD + col) =
            make_float2(rtf(o[nt][0] * inv0), rtf(o[nt][1] * inv0));
        *(float2*)(Out + base + (size_t)(rg0 + 8) * DD + col) =
            make_float2(rtf(o[nt][2] * inv1), rtf(o[nt][3] * inv1));
    }
}

// ---------------------------------------------------------------------------
// out = LayerNorm(x + r)*g + be; optional tf32-rounded copy outr
// ---------------------------------------------------------------------------
__global__ void __launch_bounds__(128) ln_res_kernel(
    const float* __restrict__ x, const float* __restrict__ r,
    const float* __restrict__ g, const float* __restrict__ be,
    float* __restrict__ out, float* __restrict__ outr)
{
    int row = blockIdx.x;
    int tid = threadIdx.x;
    const float4* xp = (const float4*)(x + (size_t)row * DD);
    const float4* rp = (const float4*)(r + (size_t)row * DD);
    float4 v = xp[tid], w = rp[tid];
    v.x += w.x; v.y += w.y; v.z += w.z; v.w += w.w;
    float s  = v.x + v.y + v.z + v.w;
    float ss = v.x * v.x + v.y * v.y + v.z * v.z + v.w * v.w;
#pragma unroll
    for (int ofs = 16; ofs > 0; ofs >>= 1) {
        s  += __shfl_xor_sync(0xffffffffu, s,  ofs);
        ss += __shfl_xor_sync(0xffffffffu, ss, ofs);
    }
    __shared__ float sb[4], ssb[4];
    int wid = tid >> 5;
    if ((tid & 31) == 0) { sb[wid] = s; ssb[wid] = ss; }
    __syncthreads();
    s  = sb[0]  + sb[1]  + sb[2]  + sb[3];
    ss = ssb[0] + ssb[1] + ssb[2] + ssb[3];
    float mean = s * (1.0f / DD);
    float var  = ss * (1.0f / DD) - mean * mean;
    float rs   = rsqrtf(var + 1e-5f);
    float4 gv = ((const float4*)g)[tid];
    float4 bv = ((const float4*)be)[tid];
    float4 o4;
    o4.x = (v.x - mean) * rs * gv.x + bv.x;
    o4.y = (v.y - mean) * rs * gv.y + bv.y;
    o4.z = (v.z - mean) * rs * gv.z + bv.z;
    o4.w = (v.w - mean) * rs * gv.w + bv.w;
    ((float4*)(out + (size_t)row * DD))[tid] = o4;
    if (outr) {
        ((float4*)(outr + (size_t)row * DD))[tid] =
            make_float4(rtf(o4.x), rtf(o4.y), rtf(o4.z), rtf(o4.w));
    }
}

// ---------------------------------------------------------------------------
extern "C" void kernel_launch(void* const* d_in, const int* in_sizes, int n_in,
                              void* d_out, int out_size)
{
    const float* qe  = (const float*)d_in[0];
    const float* qa  = (const float*)d_in[1];
    const float* fr  = (const float*)d_in[2];
    const float* pe  = (const float*)d_in[3];
    const float* Wk  = (const float*)d_in[4];
    const float* bk  = (const float*)d_in[5];
    const float* Wv  = (const float*)d_in[6];
    const float* bv  = (const float*)d_in[7];
    const float* Wo  = (const float*)d_in[8];
    const float* bo  = (const float*)d_in[9];
    const float* g1  = (const float*)d_in[10];
    const float* be1 = (const float*)d_in[11];
    const float* W1  = (const float*)d_in[12];
    const float* bf1 = (const float*)d_in[13];
    const float* W2  = (const float*)d_in[14];
    const float* bf2 = (const float*)d_in[15];
    const float* g2  = (const float*)d_in[16];
    const float* be2 = (const float*)d_in[17];
    float* out = (float*)d_out;

    float *px, *py, *pxr, *pyr, *pq, *pv, *pt, *pff;
    float *pwk, *pwv, *pwo, *pw1, *pw2;
    cudaGetSymbolAddress((void**)&px,  g_x);
    cudaGetSymbolAddress((void**)&py,  g_y);
    cudaGetSymbolAddress((void**)&pxr, g_xr);
    cudaGetSymbolAddress((void**)&pyr, g_yr);
    cudaGetSymbolAddress((void**)&pq,  g_q);
    cudaGetSymbolAddress((void**)&pv,  g_v);
    cudaGetSymbolAddress((void**)&pt,  g_t);
    cudaGetSymbolAddress((void**)&pff, g_ff);
    cudaGetSymbolAddress((void**)&pwk, g_wk);
    cudaGetSymbolAddress((void**)&pwv, g_wv);
    cudaGetSymbolAddress((void**)&pwo, g_wo);
    cudaGetSymbolAddress((void**)&pw1, g_w1);
    cudaGetSymbolAddress((void**)&pw2, g_w2);

    cudaFuncSetAttribute(attn_mma_kernel,
                         cudaFuncAttributeMaxDynamicSharedMemorySize, (int)ATTN_SMEM);
    cudaFuncSetAttribute(tf32_gemm_v2<0>,
                         cudaFuncAttributeMaxDynamicSharedMemorySize, (int)GEMM_SMEM);
    cudaFuncSetAttribute(tf32_gemm_v2<1>,
                         cudaFuncAttributeMaxDynamicSharedMemorySize, (int)GEMM_SMEM);

    // pre-round all weights to tf32 (rna)
    {
        int nkk = NBLK * DD * DD / 4;      // 131072
        int nw1 = NBLK * DD * FFD / 4;     // 524288
        round_tf32_kernel<<<(nkk + 255) / 256, 256>>>((const float4*)Wk, (float4*)pwk, nkk);
        round_tf32_kernel<<<(nkk + 255) / 256, 256>>>((const float4*)Wv, (float4*)pwv, nkk);
        round_tf32_kernel<<<(nkk + 255) / 256, 256>>>((const float4*)Wo, (float4*)pwo, nkk);
        round_tf32_kernel<<<(nw1 + 255) / 256, 256>>>((const float4*)W1, (float4*)pw1, nw1);
        round_tf32_kernel<<<(nw1 + 255) / 256, 256>>>((const float4*)W2, (float4*)pw2, nw1);
    }

    add_pe_kernel<<<(BSD / 4 + 255) / 256, 256>>>(
        (const float4*)qe, (const float4*)qa, (const float4*)pe,
        (float4*)px, (float4*)py, (float4*)pxr, (float4*)pyr);

    dim3 g512(DD / 128, MTOK / 128);    // (4, 128)
    dim3 gff(FFD / 128, MTOK / 128);    // (16, 128)
    dim3 gattn(SS / 64, BB * HH);       // (8, 256)

    for (int i = 0; i < NBLK; i++) {
        const float* wki = pwk + (size_t)i * DD * DD;
        const float* wvi = pwv + (size_t)i * DD * DD;
        const float* woi = pwo + (size_t)i * DD * DD;
        const float* w1i = pw1 + (size_t)i * DD * FFD;
        const float* w2i = pw2 + (size_t)i * FFD * DD;

        // q = x @ Wk + bk  (fp32; attn rounds internally)
        tf32_gemm_v2<0><<<g512, 128, GEMM_SMEM>>>(pxr, wki, bk + i * DD, pq, MTOK, DD, DD);
        // v = y @ Wv + bv
        tf32_gemm_v2<0><<<g512, 128, GEMM_SMEM>>>(pyr, wvi, bv + i * DD, pv, MTOK, DD, DD);
        // attention -> pt (tf32-rounded output)
        attn_mma_kernel<<<gattn, 128, ATTN_SMEM>>>(pq, pv, fr, pt);
        // proj = attn @ Wo + bo -> pq (fp32)
        tf32_gemm_v2<0><<<g512, 128, GEMM_SMEM>>>(pt, woi, bo + i * DD, pq, MTOK, DD, DD);
        // x = LN(x + proj); xr = tf32(x)
        ln_res_kernel<<<MTOK, 128>>>(px, pq, g1 + i * DD, be1 + i * DD, px, pxr);
        // hidden = relu(x @ W1 + bf1), tf32-rounded
        tf32_gemm_v2<1><<<gff, 128, GEMM_SMEM>>>(pxr, w1i, bf1 + i * FFD, pff, MTOK, FFD, DD);
        // ffn = hidden @ W2 + bf2 -> pt (fp32)
        tf32_gemm_v2<0><<<g512, 128, GEMM_SMEM>>>(pff, w2i, bf2 + i * DD, pt, MTOK, DD, FFD);
        // x = LN(x + ffn)
        float* dst = (i == NBLK - 1) ? out : px;
        float* dr  = (i == NBLK - 1) ? nullptr : pxr;
        ln_res_kernel<<<MTOK, 128>>>(px, pt, g2 + i * DD, be2 + i * DD, dst, dr);
    }
}

// round 9
// speedup vs baseline: 1.3633x; 1.3633x over previous
#include <cuda_runtime.h>
#include <math.h>
#include <stdint.h>

// Problem constants
#define BB   32
#define SS   512
#define DD   512
#define HH   8
#define DKK  64
#define FFD  2048
#define NBLK 2
#define MTOK (BB*SS)            // 16384 token rows
#define BSD  (BB*SS*DD)         // 8388608
#define BSF  (BB*SS*FFD)        // 33554432

// Scratch (static device globals — no allocation allowed)
__device__ float g_x[BSD];
__device__ float g_y[BSD];
__device__ float g_xr[BSD];
__device__ float g_yr[BSD];
__device__ float g_q[BSD];
__device__ float g_v[BSD];
__device__ float g_t[BSD];
__device__ float g_ff[BSF];
__device__ float g_wk[NBLK*DD*DD];
__device__ float g_wv[NBLK*DD*DD];
__device__ float g_wo[NBLK*DD*DD];
__device__ float g_w1[NBLK*DD*FFD];
__device__ float g_w2[NBLK*FFD*DD];

// ---------------------------------------------------------------------------
// helpers
// ---------------------------------------------------------------------------
__device__ __forceinline__ uint32_t to_tf32(float x) {
    uint32_t y;
    asm("cvt.rna.tf32.f32 %0, %1;" : "=r"(y) : "f"(x));
    return y;
}
__device__ __forceinline__ float rtf(float x) {
    return __uint_as_float(to_tf32(x));
}
__device__ __forceinline__ void mma_tf32(float c[4],
                                         uint32_t a0, uint32_t a1,
                                         uint32_t a2, uint32_t a3,
                                         uint32_t b0, uint32_t b1)
{
    asm volatile(
        "mma.sync.aligned.m16n8k8.row.col.f32.tf32.tf32.f32 "
        "{%0,%1,%2,%3}, {%4,%5,%6,%7}, {%8,%9}, {%0,%1,%2,%3};"
        : "+f"(c[0]), "+f"(c[1]), "+f"(c[2]), "+f"(c[3])
        : "r"(a0), "r"(a1), "r"(a2), "r"(a3), "r"(b0), "r"(b1));
}
__device__ __forceinline__ void cp_async16(uint32_t smem_addr, const void* gptr) {
    asm volatile("cp.async.cg.shared.global [%0], [%1], 16;"
                 :: "r"(smem_addr), "l"(gptr));
}
__device__ __forceinline__ void cp_commit() {
    asm volatile("cp.async.commit_group;");
}
template<int N>
__device__ __forceinline__ void cp_wait() {
    asm volatile("cp.async.wait_group %0;" :: "n"(N));
}

// ---------------------------------------------------------------------------
// round-copy: out = tf32_rna(in)
// ---------------------------------------------------------------------------
__global__ void round_tf32_kernel(const float4* __restrict__ in,
                                  float4* __restrict__ out, int n4)
{
    int i = blockIdx.x * blockDim.x + threadIdx.x;
    if (i >= n4) return;
    float4 v = in[i];
    v.x = rtf(v.x); v.y = rtf(v.y); v.z = rtf(v.z); v.w = rtf(v.w);
    out[i] = v;
}

// ---------------------------------------------------------------------------
// x = qe+pe, y = qa+pe (fp32) + tf32-rounded copies xr, yr
// ---------------------------------------------------------------------------
__global__ void add_pe_kernel(const float4* __restrict__ qe,
                              const float4* __restrict__ qa,
                              const float4* __restrict__ pe,
                              float4* __restrict__ x,  float4* __restrict__ y,
                              float4* __restrict__ xr, float4* __restrict__ yr)
{
    int i = blockIdx.x * blockDim.x + threadIdx.x;
    const int n4 = BSD / 4;
    if (i >= n4) return;
    int pi = i & (SS * DD / 4 - 1);
    float4 p = pe[pi];
    float4 a = qe[i];
    a.x += p.x; a.y += p.y; a.z += p.z; a.w += p.w;
    x[i] = a;
    xr[i] = make_float4(rtf(a.x), rtf(a.y), rtf(a.z), rtf(a.w));
    float4 b = qa[i];
    b.x += p.x; b.y += p.y; b.z += p.z; b.w += p.w;
    y[i] = b;
    yr[i] = make_float4(rtf(b.x), rtf(b.y), rtf(b.z), rtf(b.w));
}

// ---------------------------------------------------------------------------
// Pipelined TF32 GEMM v3: C[M,N] = A[M,K] @ W[K,N] + bias[N]
// R6 tile config (256 threads, 2x4 warps, 64x32 warp tiles, 2 CTAs/SM)
// + 3-stage cp.async pipeline. Dual input set selected by blockIdx.z
// (lets independent same-shape GEMMs share one launch).
// As: [128][36]  (frag addr 4*grp+tig mod 32 -> conflict-free)
// Bs: [32][136]  (frag addr 8*tig+grp mod 32 -> conflict-free)
// MODE 0: fp32 out. MODE 1: ReLU + tf32-round out.
// ---------------------------------------------------------------------------
#define AST 36
#define BST 136
#define ASZ (128 * AST)
#define BSZ (32 * BST)
#define STGF (ASZ + BSZ)                    // floats per stage (8960)
#define NSTG 3
#define GEMM_SMEM (NSTG * STGF * sizeof(float))   // 107520 B

template<int MODE>
__global__ void __launch_bounds__(256, 2) tf32_gemm_v3(
    const float* __restrict__ A0, const float* __restrict__ W0,
    const float* __restrict__ b0p, float* __restrict__ C0,
    const float* __restrict__ A1, const float* __restrict__ W1p,
    const float* __restrict__ b1p, float* __restrict__ C1,
    int M, int N, int K)
{
    extern __shared__ float smf[];

    const float* A    = blockIdx.z ? A1  : A0;
    const float* W    = blockIdx.z ? W1p : W0;
    const float* bias = blockIdx.z ? b1p : b0p;
    float*       C    = blockIdx.z ? C1  : C0;

    const int tid   = threadIdx.x;
    const int lane  = tid & 31;
    const int wid   = tid >> 5;
    const int wm    = wid & 1;
    const int wn    = wid >> 1;
    const int grp   = lane >> 2;
    const int tig   = lane & 3;
    const int m0    = blockIdx.y * 128;
    const int n0    = blockIdx.x * 128;

    const uint32_t sS = (uint32_t)__cvta_generic_to_shared(smf);

    const int a_row = tid >> 1;            // 0..127
    const int a_c0  = (tid & 1) * 16;      // 0 or 16
    const int b_row = tid >> 5;            // 0..7 base (4 iters of +8)
    const int b_c4  = lane * 4;            // 0..124

    float acc[4][4][4];
#pragma unroll
    for (int i = 0; i < 4; i++)
#pragma unroll
        for (int j = 0; j < 4; j++)
#pragma unroll
            for (int r = 0; r < 4; r++) acc[i][j][r] = 0.f;

    const int nk = K >> 5;

    auto load_stage = [&](int stg, int k0) {
        const uint32_t sb = sS + (uint32_t)(stg * STGF * 4);
        const float* ga = A + (size_t)(m0 + a_row) * K + k0 + a_c0;
        uint32_t da = sb + (uint32_t)((a_row * AST + a_c0) * 4);
        cp_async16(da,      ga);
        cp_async16(da + 16, ga + 4);
        cp_async16(da + 32, ga + 8);
        cp_async16(da + 48, ga + 12);
#pragma unroll
        for (int it = 0; it < 4; it++) {
            int row = b_row + it * 8;
            const float* gb = W + (size_t)(k0 + row) * N + n0 + b_c4;
            uint32_t db = sb + (uint32_t)((ASZ + row * BST + b_c4) * 4);
            cp_async16(db, gb);
        }
    };

    // prologue: fill stages 0,1
    load_stage(0, 0);
    cp_commit();
    load_stage(1, 32);
    cp_commit();

    for (int kt = 0; kt < nk; kt++) {
        if (kt + NSTG - 1 < nk) {
            int s = kt + NSTG - 1;
            load_stage(s % NSTG, s * 32);
        }
        cp_commit();                 // one group per iteration (maybe empty)
        cp_wait<NSTG - 1>();         // stage kt's group complete
        __syncthreads();

        const float* pA = smf + (kt % NSTG) * STGF;
        const float* pB = pA + ASZ;

#pragma unroll
        for (int kk = 0; kk < 32; kk += 8) {
            uint32_t af[4][4];
            uint32_t bf[4][2];
#pragma unroll
            for (int mt = 0; mt < 4; mt++) {
                int mr = wm * 64 + mt * 16 + grp;
                af[mt][0] = __float_as_uint(pA[(mr    ) * AST + kk + tig    ]);
                af[mt][1] = __float_as_uint(pA[(mr + 8) * AST + kk + tig    ]);
                af[mt][2] = __float_as_uint(pA[(mr    ) * AST + kk + tig + 4]);
                af[mt][3] = __float_as_uint(pA[(mr + 8) * AST + kk + tig + 4]);
            }
#pragma unroll
            for (int nt = 0; nt < 4; nt++) {
                int nc = wn * 32 + nt * 8 + grp;
                bf[nt][0] = __float_as_uint(pB[(kk + tig    ) * BST + nc]);
                bf[nt][1] = __float_as_uint(pB[(kk + tig + 4) * BST + nc]);
            }
#pragma unroll
            for (int mt = 0; mt < 4; mt++)
#pragma unroll
                for (int nt = 0; nt < 4; nt++)
                    mma_tf32(acc[mt][nt],
                             af[mt][0], af[mt][1], af[mt][2], af[mt][3],
                             bf[nt][0], bf[nt][1]);
        }
        __syncthreads();   // WAR: next iter refills stage (kt+3)%3 == kt%3
    }

    // Epilogue
#pragma unroll
    for (int mt = 0; mt < 4; mt++) {
#pragma unroll
        for (int nt = 0; nt < 4; nt++) {
            int row = m0 + wm * 64 + mt * 16 + grp;
            int col = n0 + wn * 32 + nt * 8 + tig * 2;
            float bb0 = bias[col], bb1 = bias[col + 1];
            float v0 = acc[mt][nt][0] + bb0;
            float v1 = acc[mt][nt][1] + bb1;
            float v2 = acc[mt][nt][2] + bb0;
            float v3 = acc[mt][nt][3] + bb1;
            if (MODE == 1) {
                v0 = rtf(fmaxf(v0, 0.f)); v1 = rtf(fmaxf(v1, 0.f));
                v2 = rtf(fmaxf(v2, 0.f)); v3 = rtf(fmaxf(v3, 0.f));
            }
            *(float2*)(C + (size_t)row * N + col)       = make_float2(v0, v1);
            *(float2*)(C + (size_t)(row + 8) * N + col) = make_float2(v2, v3);
        }
    }
}

// ---------------------------------------------------------------------------
// TF32 tensor-core flash attention. Heavy tiles scheduled first.
// Output tf32-rounded (feeds Wo GEMM).
// ---------------------------------------------------------------------------
#define QK_PAD 68
#define V_PAD  72
#define ATTN_SMEM ((2 * 64 * QK_PAD + 64 * V_PAD) * sizeof(uint32_t))

__global__ void __launch_bounds__(128, 4) attn_mma_kernel(
    const float* __restrict__ Q, const float* __restrict__ V,
    const float* __restrict__ FR, float* __restrict__ Out)
{
    extern __shared__ uint32_t smu[];
    uint32_t* Qs = smu;
    uint32_t* Ks = smu + 64 * QK_PAD;
    uint32_t* Vs = smu + 2 * 64 * QK_PAD;

    const int qt   = gridDim.x - 1 - blockIdx.x;   // heavy-first
    const int bh   = blockIdx.y;
    const int b    = bh >> 3;
    const int h    = bh & 7;
    const int tid  = threadIdx.x;
    const int lane = tid & 31;
    const int w    = tid >> 5;
    const int grp  = lane >> 2;
    const int tig  = lane & 3;
    const int q0   = qt * 64;
    const size_t base = (size_t)b * SS * DD + (size_t)h * DKK;

#pragma unroll
    for (int j = 0; j < 8; j++) {
        int idx = j * 128 + tid;
        int r   = idx >> 4;
        int c4  = (idx & 15) * 4;
        float4 v = *(const float4*)(Q + base + (size_t)(q0 + r) * DD + c4);
        uint32_t* d = Qs + r * QK_PAD + c4;
        d[0] = to_tf32(v.x); d[1] = to_tf32(v.y);
        d[2] = to_tf32(v.z); d[3] = to_tf32(v.w);
    }

    const int rg0 = q0 + w * 16 + grp;
    const float frs0 = FR[b * SS + rg0]     * 0.125f;
    const float frs1 = FR[b * SS + rg0 + 8] * 0.125f;

    float m0 = -3.0e38f, m1 = -3.0e38f, l0 = 0.f, l1 = 0.f;
    float o[8][4];
#pragma unroll
    for (int nt = 0; nt < 8; nt++)
#pragma unroll
        for (int r = 0; r < 4; r++) o[nt][r] = 0.f;

    for (int kt = 0; kt <= qt; kt++) {
        __syncthreads();
#pragma unroll
        for (int j = 0; j < 8; j++) {
            int idx = j * 128 + tid;
            int r   = idx >> 4;
            int c4  = (idx & 15) * 4;
            float4 kv = *(const float4*)(Q + base + (size_t)(kt * 64 + r) * DD + c4);
            float4 vv = *(const float4*)(V + base + (size_t)(kt * 64 + r) * DD + c4);
            uint32_t* kd = Ks + r * QK_PAD + c4;
            uint32_t* vd = Vs + r * V_PAD  + c4;
            kd[0] = to_tf32(kv.x); kd[1] = to_tf32(kv.y);
            kd[2] = to_tf32(kv.z); kd[3] = to_tf32(kv.w);
            vd[0] = to_tf32(vv.x); vd[1] = to_tf32(vv.y);
            vd[2] = to_tf32(vv.z); vd[3] = to_tf32(vv.w);
        }
        __syncthreads();

        float sc[8][4];
#pragma unroll
        for (int nt = 0; nt < 8; nt++)
#pragma unroll
            for (int r = 0; r < 4; r++) sc[nt][r] = 0.f;

#pragma unroll
        for (int kk = 0; kk < 64; kk += 8) {
            const int mr = w * 16 + grp;
            uint32_t a0 = Qs[(mr    ) * QK_PAD + kk + tig    ];
            uint32_t a1 = Qs[(mr + 8) * QK_PAD + kk + tig    ];
            uint32_t a2 = Qs[(mr    ) * QK_PAD + kk + tig + 4];
            uint32_t a3 = Qs[(mr + 8) * QK_PAD + kk + tig + 4];
#pragma unroll
            for (int nt = 0; nt < 8; nt++) {
                uint32_t b0 = Ks[(nt * 8 + grp) * QK_PAD + kk + tig    ];
                uint32_t b1 = Ks[(nt * 8 + grp) * QK_PAD + kk + tig + 4];
                mma_tf32(sc[nt], a0, a1, a2, a3, b0, b1);
            }
        }

        const bool diag = (kt == qt);
        float mx0 = -3.0e38f, mx1 = -3.0e38f;
#pragma unroll
        for (int nt = 0; nt < 8; nt++) {
            int cg = kt * 64 + nt * 8 + 2 * tig;
            float s0 = sc[nt][0] * frs0;
            float s1 = sc[nt][1] * frs0;
            float s2 = sc[nt][2] * frs1;
            float s3 = sc[nt][3] * frs1;
            if (diag) {
                if (cg     >= rg0)     s0 = -1e30f;
                if (cg + 1 >= rg0)     s1 = -1e30f;
                if (cg     >= rg0 + 8) s2 = -1e30f;
                if (cg + 1 >= rg0 + 8) s3 = -1e30f;
            }
            sc[nt][0] = s0; sc[nt][1] = s1; sc[nt][2] = s2; sc[nt][3] = s3;
            mx0 = fmaxf(mx0, fmaxf(s0, s1));
            mx1 = fmaxf(mx1, fmaxf(s2, s3));
        }
        mx0 = fmaxf(mx0, __shfl_xor_sync(0xffffffffu, mx0, 1));
        mx0 = fmaxf(mx0, __shfl_xor_sync(0xffffffffu, mx0, 2));
        mx1 = fmaxf(mx1, __shfl_xor_sync(0xffffffffu, mx1, 1));
        mx1 = fmaxf(mx1, __shfl_xor_sync(0xffffffffu, mx1, 2));

        float mn0 = fmaxf(m0, mx0);
        float mn1 = fmaxf(m1, mx1);
        float al0 = __expf(m0 - mn0);
        float al1 = __expf(m1 - mn1);
        m0 = mn0; m1 = mn1;

        float su0 = 0.f, su1 = 0.f;
        uint32_t pu[8][4];
#pragma unroll
        for (int nt = 0; nt < 8; nt++) {
            float p0 = __expf(sc[nt][0] - mn0);
            float p1 = __expf(sc[nt][1] - mn0);
            float p2 = __expf(sc[nt][2] - mn1);
            float p3 = __expf(sc[nt][3] - mn1);
            su0 += p0 + p1;
            su1 += p2 + p3;
            pu[nt][0] = to_tf32(p0); pu[nt][1] = to_tf32(p1);
            pu[nt][2] = to_tf32(p2); pu[nt][3] = to_tf32(p3);
        }
        su0 += __shfl_xor_sync(0xffffffffu, su0, 1);
        su0 += __shfl_xor_sync(0xffffffffu, su0, 2);
        su1 += __shfl_xor_sync(0xffffffffu, su1, 1);
        su1 += __shfl_xor_sync(0xffffffffu, su1, 2);
        l0 = l0 * al0 + su0;
        l1 = l1 * al1 + su1;
#pragma unroll
        for (int nt = 0; nt < 8; nt++) {
            o[nt][0] *= al0; o[nt][1] *= al0;
            o[nt][2] *= al1; o[nt][3] *= al1;
        }

        const int srcbase = (lane & ~3) | (tig >> 1);
        const int odd = tig & 1;
#pragma unroll
        for (int j = 0; j < 8; j++) {
            uint32_t x0a = __shfl_sync(0xffffffffu, pu[j][0], srcbase);
            uint32_t x1a = __shfl_sync(0xffffffffu, pu[j][1], srcbase);
            uint32_t x2a = __shfl_sync(0xffffffffu, pu[j][2], srcbase);
            uint32_t x3a = __shfl_sync(0xffffffffu, pu[j][3], srcbase);
            uint32_t x0b = __shfl_sync(0xffffffffu, pu[j][0], srcbase + 2);
            uint32_t x1b = __shfl_sync(0xffffffffu, pu[j][1], srcbase + 2);
            uint32_t x2b = __shfl_sync(0xffffffffu, pu[j][2], srcbase + 2);
            uint32_t x3b = __shfl_sync(0xffffffffu, pu[j][3], srcbase + 2);
            uint32_t a0 = odd ? x1a : x0a;
            uint32_t a1 = odd ? x3a : x2a;
            uint32_t a2 = odd ? x1b : x0b;
            uint32_t a3 = odd ? x3b : x2b;
#pragma unroll
            for (int nt = 0; nt < 8; nt++) {
                uint32_t b0 = Vs[(j * 8 + tig    ) * V_PAD + nt * 8 + grp];
                uint32_t b1 = Vs[(j * 8 + tig + 4) * V_PAD + nt * 8 + grp];
                mma_tf32(o[nt], a0, a1, a2, a3, b0, b1);
            }
        }
    }

    float inv0 = (rg0 == 0) ? 0.f : (1.0f / l0);
    float inv1 = 1.0f / l1;
#pragma unroll
    for (int nt = 0; nt < 8; nt++) {
        int col = nt * 8 + tig * 2;
        *(float2*)(Out + base + (size_t)(rg0    ) * DD + col) =
            make_float2(rtf(o[nt][0] * inv0), rtf(o[nt][1] * inv0));
        *(float2*)(Out + base + (size_t)(rg0 + 8) * DD + col) =
            make_float2(rtf(o[nt][2] * inv1), rtf(o[nt][3] * inv1));
    }
}

// ---------------------------------------------------------------------------
// out = LayerNorm(x + r)*g + be; optional tf32-rounded copy outr
// ---------------------------------------------------------------------------
__global__ void __launch_bounds__(128) ln_res_kernel(
    const float* __restrict__ x, const float* __restrict__ r,
    const float* __restrict__ g, const float* __restrict__ be,
    float* __restrict__ out, float* __restrict__ outr)
{
    int row = blockIdx.x;
    int tid = threadIdx.x;
    const float4* xp = (const float4*)(x + (size_t)row * DD);
    const float4* rp = (const float4*)(r + (size_t)row * DD);
    float4 v = xp[tid], w = rp[tid];
    v.x += w.x; v.y += w.y; v.z += w.z; v.w += w.w;
    float s  = v.x + v.y + v.z + v.w;
    float ss = v.x * v.x + v.y * v.y + v.z * v.z + v.w * v.w;
#pragma unroll
    for (int ofs = 16; ofs > 0; ofs >>= 1) {
        s  += __shfl_xor_sync(0xffffffffu, s,  ofs);
        ss += __shfl_xor_sync(0xffffffffu, ss, ofs);
    }
    __shared__ float sb[4], ssb[4];
    int wid = tid >> 5;
    if ((tid & 31) == 0) { sb[wid] = s; ssb[wid] = ss; }
    __syncthreads();
    s  = sb[0]  + sb[1]  + sb[2]  + sb[3];
    ss = ssb[0] + ssb[1] + ssb[2] + ssb[3];
    float mean = s * (1.0f / DD);
    float var  = ss * (1.0f / DD) - mean * mean;
    float rs   = rsqrtf(var + 1e-5f);
    float4 gv = ((const float4*)g)[tid];
    float4 bv = ((const float4*)be)[tid];
    float4 o4;
    o4.x = (v.x - mean) * rs * gv.x + bv.x;
    o4.y = (v.y - mean) * rs * gv.y + bv.y;
    o4.z = (v.z - mean) * rs * gv.z + bv.z;
    o4.w = (v.w - mean) * rs * gv.w + bv.w;
    ((float4*)(out + (size_t)row * DD))[tid] = o4;
    if (outr) {
        ((float4*)(outr + (size_t)row * DD))[tid] =
            make_float4(rtf(o4.x), rtf(o4.y), rtf(o4.z), rtf(o4.w));
    }
}

// ---------------------------------------------------------------------------
extern "C" void kernel_launch(void* const* d_in, const int* in_sizes, int n_in,
                              void* d_out, int out_size)
{
    const float* qe  = (const float*)d_in[0];
    const float* qa  = (const float*)d_in[1];
    const float* fr  = (const float*)d_in[2];
    const float* pe  = (const float*)d_in[3];
    const float* Wk  = (const float*)d_in[4];
    const float* bk  = (const float*)d_in[5];
    const float* Wv  = (const float*)d_in[6];
    const float* bv  = (const float*)d_in[7];
    const float* Wo  = (const float*)d_in[8];
    const float* bo  = (const float*)d_in[9];
    const float* g1  = (const float*)d_in[10];
    const float* be1 = (const float*)d_in[11];
    const float* W1  = (const float*)d_in[12];
    const float* bf1 = (const float*)d_in[13];
    const float* W2  = (const float*)d_in[14];
    const float* bf2 = (const float*)d_in[15];
    const float* g2  = (const float*)d_in[16];
    const float* be2 = (const float*)d_in[17];
    float* out = (float*)d_out;

    float *px, *py, *pxr, *pyr, *pq, *pv, *pt, *pff;
    float *pwk, *pwv, *pwo, *pw1, *pw2;
    cudaGetSymbolAddress((void**)&px,  g_x);
    cudaGetSymbolAddress((void**)&py,  g_y);
    cudaGetSymbolAddress((void**)&pxr, g_xr);
    cudaGetSymbolAddress((void**)&pyr, g_yr);
    cudaGetSymbolAddress((void**)&pq,  g_q);
    cudaGetSymbolAddress((void**)&pv,  g_v);
    cudaGetSymbolAddress((void**)&pt,  g_t);
    cudaGetSymbolAddress((void**)&pff, g_ff);
    cudaGetSymbolAddress((void**)&pwk, g_wk);
    cudaGetSymbolAddress((void**)&pwv, g_wv);
    cudaGetSymbolAddress((void**)&pwo, g_wo);
    cudaGetSymbolAddress((void**)&pw1, g_w1);
    cudaGetSymbolAddress((void**)&pw2, g_w2);

    cudaFuncSetAttribute(attn_mma_kernel,
                         cudaFuncAttributeMaxDynamicSharedMemorySize, (int)ATTN_SMEM);
    cudaFuncSetAttribute(tf32_gemm_v3<0>,
                         cudaFuncAttributeMaxDynamicSharedMemorySize, (int)GEMM_SMEM);
    cudaFuncSetAttribute(tf32_gemm_v3<1>,
                         cudaFuncAttributeMaxDynamicSharedMemorySize, (int)GEMM_SMEM);

    // pre-round all weights to tf32 (rna)
    {
        int nkk = NBLK * DD * DD / 4;
        int nw1 = NBLK * DD * FFD / 4;
        round_tf32_kernel<<<(nkk + 255) / 256, 256>>>((const float4*)Wk, (float4*)pwk, nkk);
        round_tf32_kernel<<<(nkk + 255) / 256, 256>>>((const float4*)Wv, (float4*)pwv, nkk);
        round_tf32_kernel<<<(nkk + 255) / 256, 256>>>((const float4*)Wo, (float4*)pwo, nkk);
        round_tf32_kernel<<<(nw1 + 255) / 256, 256>>>((const float4*)W1, (float4*)pw1, nw1);
        round_tf32_kernel<<<(nw1 + 255) / 256, 256>>>((const float4*)W2, (float4*)pw2, nw1);
    }

    add_pe_kernel<<<(BSD / 4 + 255) / 256, 256>>>(
        (const float4*)qe, (const float4*)qa, (const float4*)pe,
        (float4*)px, (float4*)py, (float4*)pxr, (float4*)pyr);

    dim3 g512 (DD / 128, MTOK / 128, 1);   // (4, 128)
    dim3 g512z(DD / 128, MTOK / 128, 2);   // merged q & v
    dim3 gff  (FFD / 128, MTOK / 128, 1);  // (16, 128)
    dim3 gattn(SS / 64, BB * HH);          // (8, 256)

    for (int i = 0; i < NBLK; i++) {
        const float* wki = pwk + (size_t)i * DD * DD;
        const float* wvi = pwv + (size_t)i * DD * DD;
        const float* woi = pwo + (size_t)i * DD * DD;
        const float* w1i = pw1 + (size_t)i * DD * FFD;
        const float* w2i = pw2 + (size_t)i * FFD * DD;

        // merged: z=0 -> q = x@Wk + bk ; z=1 -> v = y@Wv + bv
        tf32_gemm_v3<0><<<g512z, 256, GEMM_SMEM>>>(
            pxr, wki, bk + i * DD, pq,
            pyr, wvi, bv + i * DD, pv, MTOK, DD, DD);
        // attention -> pt (tf32-rounded)
        attn_mma_kernel<<<gattn, 128, ATTN_SMEM>>>(pq, pv, fr, pt);
        // proj = attn @ Wo + bo -> pq
        tf32_gemm_v3<0><<<g512, 256, GEMM_SMEM>>>(
            pt, woi, bo + i * DD, pq,
            pt, woi, bo + i * DD, pq, MTOK, DD, DD);
        // x = LN(x + proj); xr = tf32(x)
        ln_res_kernel<<<MTOK, 128>>>(px, pq, g1 + i * DD, be1 + i * DD, px, pxr);
        // hidden = relu(x @ W1 + bf1), tf32-rounded
        tf32_gemm_v3<1><<<gff, 256, GEMM_SMEM>>>(
            pxr, w1i, bf1 + i * FFD, pff,
            pxr, w1i, bf1 + i * FFD, pff, MTOK, FFD, DD);
        // ffn = hidden @ W2 + bf2 -> pt
        tf32_gemm_v3<0><<<g512, 256, GEMM_SMEM>>>(
            pff, w2i, bf2 + i * DD, pt,
            pff, w2i, bf2 + i * DD, pt, MTOK, DD, FFD);
        // x = LN(x + ffn)
        float* dst = (i == NBLK - 1) ? out : px;
        float* dr  = (i == NBLK - 1) ? nullptr : pxr;
        ln_res_kernel<<<MTOK, 128>>>(px, pt, g2 + i * DD, be2 + i * DD, dst, dr);
    }
}

// round 10
// speedup vs baseline: 2.0595x; 1.5107x over previous
#include <cuda_runtime.h>
#include <cuda_fp16.h>
#include <math.h>
#include <stdint.h>

// Problem constants
#define BB   32
#define SS   512
#define DD   512
#define HH   8
#define DKK  64
#define FFD  2048
#define NBLK 2
#define MTOK (BB*SS)            // 16384 token rows
#define BSD  (BB*SS*DD)         // 8388608
#define BSF  (BB*SS*FFD)        // 33554432

// Scratch (static device globals — no allocation allowed)
__device__ float  g_x[BSD];          // residual stream (fp32)
__device__ float  g_q[BSD];          // q (fp32, attn input)
__device__ float  g_v[BSD];          // v (fp32, attn input)
__device__ float  g_t[BSD];          // fp32 temp (proj / ffn out)
__device__ __half g_xh[BSD];         // fp16 activations
__device__ __half g_yh[BSD];
__device__ __half g_ah[BSD];         // attn output (fp16)
__device__ __half g_fh[BSF];         // ffn hidden (fp16)
__device__ __half g_wkt[NBLK*DD*DD]; // transposed fp16 weights [N][K]
__device__ __half g_wvt[NBLK*DD*DD];
__device__ __half g_wot[NBLK*DD*DD];
__device__ __half g_w1t[NBLK*DD*FFD];
__device__ __half g_w2t[NBLK*FFD*DD];

// ---------------------------------------------------------------------------
// helpers
// ---------------------------------------------------------------------------
__device__ __forceinline__ uint32_t to_tf32(float x) {
    uint32_t y;
    asm("cvt.rna.tf32.f32 %0, %1;" : "=r"(y) : "f"(x));
    return y;
}
__device__ __forceinline__ void mma_tf32(float c[4],
                                         uint32_t a0, uint32_t a1,
                                         uint32_t a2, uint32_t a3,
                                         uint32_t b0, uint32_t b1)
{
    asm volatile(
        "mma.sync.aligned.m16n8k8.row.col.f32.tf32.tf32.f32 "
        "{%0,%1,%2,%3}, {%4,%5,%6,%7}, {%8,%9}, {%0,%1,%2,%3};"
        : "+f"(c[0]), "+f"(c[1]), "+f"(c[2]), "+f"(c[3])
        : "r"(a0), "r"(a1), "r"(a2), "r"(a3), "r"(b0), "r"(b1));
}
__device__ __forceinline__ void mma_f16(float c[4],
                                        uint32_t a0, uint32_t a1,
                                        uint32_t a2, uint32_t a3,
                                        uint32_t b0, uint32_t b1)
{
    asm volatile(
        "mma.sync.aligned.m16n8k16.row.col.f32.f16.f16.f32 "
        "{%0,%1,%2,%3}, {%4,%5,%6,%7}, {%8,%9}, {%0,%1,%2,%3};"
        : "+f"(c[0]), "+f"(c[1]), "+f"(c[2]), "+f"(c[3])
        : "r"(a0), "r"(a1), "r"(a2), "r"(a3), "r"(b0), "r"(b1));
}
__device__ __forceinline__ void cp_async16(uint32_t smem_addr, const void* gptr) {
    asm volatile("cp.async.cg.shared.global [%0], [%1], 16;"
                 :: "r"(smem_addr), "l"(gptr));
}
__device__ __forceinline__ void cp_commit() {
    asm volatile("cp.async.commit_group;");
}
template<int N>
__device__ __forceinline__ void cp_wait() {
    asm volatile("cp.async.wait_group %0;" :: "n"(N));
}

// ---------------------------------------------------------------------------
// One-shot weight transpose + fp16 convert for ALL weights.
// W[K][N] fp32 -> Wt[N][K] fp16.  z in [0,10): (matrix, block) pairs.
// Grid (64, 64, 10), block (32, 8). Out-of-range blocks return early.
// ---------------------------------------------------------------------------
__global__ void wtrans_all_kernel(
    const float* __restrict__ Wk, const float* __restrict__ Wv,
    const float* __restrict__ Wo, const float* __restrict__ W1,
    const float* __restrict__ W2,
    __half* __restrict__ twk, __half* __restrict__ twv,
    __half* __restrict__ two, __half* __restrict__ tw1,
    __half* __restrict__ tw2)
{
    const int z   = blockIdx.z;
    const int blk = z & 1;
    const float* W; __half* T; int K, N;
    switch (z >> 1) {
        case 0: W = Wk + (size_t)blk * DD * DD;  T = twk + (size_t)blk * DD * DD;  K = DD;  N = DD;  break;
        case 1: W = Wv + (size_t)blk * DD * DD;  T = twv + (size_t)blk * DD * DD;  K = DD;  N = DD;  break;
        case 2: W = Wo + (size_t)blk * DD * DD;  T = two + (size_t)blk * DD * DD;  K = DD;  N = DD;  break;
        case 3: W = W1 + (size_t)blk * DD * FFD; T = tw1 + (size_t)blk * DD * FFD; K = DD;  N = FFD; break;
        default:W = W2 + (size_t)blk * FFD * DD; T = tw2 + (size_t)blk * FFD * DD; K = FFD; N = DD;  break;
    }
    const int n0 = blockIdx.x * 32;
    const int k0 = blockIdx.y * 32;
    if (n0 >= N || k0 >= K) return;

    __shared__ float t[32][33];
    const int tx = threadIdx.x, ty = threadIdx.y;
    for (int j = ty; j < 32; j += 8)
        t[j][tx] = W[(size_t)(k0 + j) * N + n0 + tx];
    __syncthreads();
    for (int j = ty; j < 32; j += 8)
        T[(size_t)(n0 + j) * K + k0 + tx] = __float2half_rn(t[tx][j]);
}

// ---------------------------------------------------------------------------
// x = qe+pe (fp32 residual) + fp16 copies xh, yh of both streams
// ---------------------------------------------------------------------------
__global__ void add_pe_kernel(const float4* __restrict__ qe,
                              const float4* __restrict__ qa,
                              const float4* __restrict__ pe,
                              float4* __restrict__ x,
                              __half* __restrict__ xh, __half* __restrict__ yh)
{
    int i = blockIdx.x * blockDim.x + threadIdx.x;
    const int n4 = BSD / 4;
    if (i >= n4) return;
    int pi = i & (SS * DD / 4 - 1);
    float4 p = pe[pi];
    float4 a = qe[i];
    a.x += p.x; a.y += p.y; a.z += p.z; a.w += p.w;
    x[i] = a;
    ((__half2*)(xh + 4 * (size_t)i))[0] = __floats2half2_rn(a.x, a.y);
    ((__half2*)(xh + 4 * (size_t)i))[1] = __floats2half2_rn(a.z, a.w);
    float4 b = qa[i];
    b.x += p.x; b.y += p.y; b.z += p.z; b.w += p.w;
    ((__half2*)(yh + 4 * (size_t)i))[0] = __floats2half2_rn(b.x, b.y);
    ((__half2*)(yh + 4 * (size_t)i))[1] = __floats2half2_rn(b.z, b.w);
}

// ---------------------------------------------------------------------------
// FP16 tensor-core GEMM: C[M,N] = A[M,K] @ Wt[N,K]^T + bias[N]
// A fp16 [M][K], Wt fp16 [N][K] (pre-transposed). fp32 accumulate.
// 256 threads (2x4 warps, 64x32 warp tiles), BK=32, 3-stage cp.async.
// Smem: A/B tiles 128 rows x 32 halves, row stride 40 halves (conflict-free).
// blockIdx.z selects between two independent input sets (merged launches).
// MODE 0: fp32 out. MODE 1: ReLU + fp16 out.
// ---------------------------------------------------------------------------
#define HST 40
#define HTILE (128 * HST)                  // halves per tile (5120)
#define STGH (2 * HTILE)                   // halves per stage (A+B)
#define NSTG 3
#define GEMM_SMEM (NSTG * STGH * sizeof(__half))   // 61440 B

template<int MODE>
__global__ void __launch_bounds__(256, 2) f16_gemm(
    const __half* __restrict__ A0, const __half* __restrict__ W0,
    const float* __restrict__ b0p, void* __restrict__ C0,
    const __half* __restrict__ A1, const __half* __restrict__ W1p,
    const float* __restrict__ b1p, void* __restrict__ C1,
    int M, int N, int K)
{
    extern __shared__ __half smh[];

    const __half* A    = blockIdx.z ? A1  : A0;
    const __half* W    = blockIdx.z ? W1p : W0;
    const float*  bias = blockIdx.z ? b1p : b0p;
    void*         C    = blockIdx.z ? C1  : C0;

    const int tid  = threadIdx.x;
    const int lane = tid & 31;
    const int wid  = tid >> 5;
    const int wm   = wid & 1;
    const int wn   = wid >> 1;
    const int grp  = lane >> 2;
    const int tig  = lane & 3;
    const int m0   = blockIdx.y * 128;
    const int n0   = blockIdx.x * 128;

    const uint32_t sS = (uint32_t)__cvta_generic_to_shared(smh);

    // loads: each tile is 128 rows x 32 halves (4x16B chunks per row)
    const int l_row = tid >> 1;            // 0..127
    const int l_h0  = (tid & 1) * 16;      // half offset 0 or 16

    float acc[4][4][4];
#pragma unroll
    for (int i = 0; i < 4; i++)
#pragma unroll
        for (int j = 0; j < 4; j++)
#pragma unroll
            for (int r = 0; r < 4; r++) acc[i][j][r] = 0.f;

    const int nk = K >> 5;

    auto load_stage = [&](int stg, int k0) {
        const uint32_t sb = sS + (uint32_t)(stg * STGH * 2);
        // A tile
        {
            const __half* ga = A + (size_t)(m0 + l_row) * K + k0 + l_h0;
            uint32_t da = sb + (uint32_t)((l_row * HST + l_h0) * 2);
            cp_async16(da,      ga);
            cp_async16(da + 16, ga + 8);
        }
        // B tile (Wt rows n0..n0+127)
        {
            const __half* gb = W + (size_t)(n0 + l_row) * K + k0 + l_h0;
            uint32_t db = sb + (uint32_t)((HTILE + l_row * HST + l_h0) * 2);
            cp_async16(db,      gb);
            cp_async16(db + 16, gb + 8);
        }
    };

    load_stage(0, 0);
    cp_commit();
    load_stage(1, 32);
    cp_commit();

    for (int kt = 0; kt < nk; kt++) {
        if (kt + NSTG - 1 < nk) {
            int s = kt + NSTG - 1;
            load_stage(s % NSTG, s * 32);
        }
        cp_commit();
        cp_wait<NSTG - 1>();
        __syncthreads();

        const __half* pA = smh + (kt % NSTG) * STGH;
        const __half* pB = pA + HTILE;

#pragma unroll
        for (int kk = 0; kk < 32; kk += 16) {
            uint32_t af[4][4];
            uint32_t bf[4][2];
#pragma unroll
            for (int mt = 0; mt < 4; mt++) {
                int mr = wm * 64 + mt * 16 + grp;
                af[mt][0] = *(const uint32_t*)(pA + (mr    ) * HST + kk + 2 * tig    );
                af[mt][1] = *(const uint32_t*)(pA + (mr + 8) * HST + kk + 2 * tig    );
                af[mt][2] = *(const uint32_t*)(pA + (mr    ) * HST + kk + 2 * tig + 8);
                af[mt][3] = *(const uint32_t*)(pA + (mr + 8) * HST + kk + 2 * tig + 8);
            }
#pragma unroll
            for (int nt = 0; nt < 4; nt++) {
                int nc = wn * 32 + nt * 8 + grp;
                bf[nt][0] = *(const uint32_t*)(pB + nc * HST + kk + 2 * tig    );
                bf[nt][1] = *(const uint32_t*)(pB + nc * HST + kk + 2 * tig + 8);
            }
#pragma unroll
            for (int mt = 0; mt < 4; mt++)
#pragma unroll
                for (int nt = 0; nt < 4; nt++)
                    mma_f16(acc[mt][nt],
                            af[mt][0], af[mt][1], af[mt][2], af[mt][3],
                            bf[nt][0], bf[nt][1]);
        }
        __syncthreads();
    }

    // Epilogue
#pragma unroll
    for (int mt = 0; mt < 4; mt++) {
#pragma unroll
        for (int nt = 0; nt < 4; nt++) {
            int row = m0 + wm * 64 + mt * 16 + grp;
            int col = n0 + wn * 32 + nt * 8 + tig * 2;
            float bb0 = bias[col], bb1 = bias[col + 1];
            float v0 = acc[mt][nt][0] + bb0;
            float v1 = acc[mt][nt][1] + bb1;
            float v2 = acc[mt][nt][2] + bb0;
            float v3 = acc[mt][nt][3] + bb1;
            if (MODE == 0) {
                float* Cf = (float*)C;
                *(float2*)(Cf + (size_t)row * N + col)       = make_float2(v0, v1);
                *(float2*)(Cf + (size_t)(row + 8) * N + col) = make_float2(v2, v3);
            } else {
                __half* Ch = (__half*)C;
                v0 = fmaxf(v0, 0.f); v1 = fmaxf(v1, 0.f);
                v2 = fmaxf(v2, 0.f); v3 = fmaxf(v3, 0.f);
                *(__half2*)(Ch + (size_t)row * N + col)       = __floats2half2_rn(v0, v1);
                *(__half2*)(Ch + (size_t)(row + 8) * N + col) = __floats2half2_rn(v2, v3);
            }
        }
    }
}

// ---------------------------------------------------------------------------
// TF32 tensor-core flash attention (R9 core; epilogue writes fp16 for Wo GEMM)
// ---------------------------------------------------------------------------
#define QK_PAD 68
#define V_PAD  72
#define ATTN_SMEM ((2 * 64 * QK_PAD + 64 * V_PAD) * sizeof(uint32_t))

__global__ void __launch_bounds__(128, 4) attn_mma_kernel(
    const float* __restrict__ Q, const float* __restrict__ V,
    const float* __restrict__ FR, __half* __restrict__ AH)
{
    extern __shared__ uint32_t smu[];
    uint32_t* Qs = smu;
    uint32_t* Ks = smu + 64 * QK_PAD;
    uint32_t* Vs = smu + 2 * 64 * QK_PAD;

    const int qt   = gridDim.x - 1 - blockIdx.x;   // heavy-first
    const int bh   = blockIdx.y;
    const int b    = bh >> 3;
    const int h    = bh & 7;
    const int tid  = threadIdx.x;
    const int lane = tid & 31;
    const int w    = tid >> 5;
    const int grp  = lane >> 2;
    const int tig  = lane & 3;
    const int q0   = qt * 64;
    const size_t base = (size_t)b * SS * DD + (size_t)h * DKK;

#pragma unroll
    for (int j = 0; j < 8; j++) {
        int idx = j * 128 + tid;
        int r   = idx >> 4;
        int c4  = (idx & 15) * 4;
        float4 v = *(const float4*)(Q + base + (size_t)(q0 + r) * DD + c4);
        uint32_t* d = Qs + r * QK_PAD + c4;
        d[0] = to_tf32(v.x); d[1] = to_tf32(v.y);
        d[2] = to_tf32(v.z); d[3] = to_tf32(v.w);
    }

    const int rg0 = q0 + w * 16 + grp;
    const float frs0 = FR[b * SS + rg0]     * 0.125f;
    const float frs1 = FR[b * SS + rg0 + 8] * 0.125f;

    float m0 = -3.0e38f, m1 = -3.0e38f, l0 = 0.f, l1 = 0.f;
    float o[8][4];
#pragma unroll
    for (int nt = 0; nt < 8; nt++)
#pragma unroll
        for (int r = 0; r < 4; r++) o[nt][r] = 0.f;

    for (int kt = 0; kt <= qt; kt++) {
        __syncthreads();
#pragma unroll
        for (int j = 0; j < 8; j++) {
            int idx = j * 128 + tid;
            int r   = idx >> 4;
            int c4  = (idx & 15) * 4;
            float4 kv = *(const float4*)(Q + base + (size_t)(kt * 64 + r) * DD + c4);
            float4 vv = *(const float4*)(V + base + (size_t)(kt * 64 + r) * DD + c4);
            uint32_t* kd = Ks + r * QK_PAD + c4;
            uint32_t* vd = Vs + r * V_PAD  + c4;
            kd[0] = to_tf32(kv.x); kd[1] = to_tf32(kv.y);
            kd[2] = to_tf32(kv.z); kd[3] = to_tf32(kv.w);
            vd[0] = to_tf32(vv.x); vd[1] = to_tf32(vv.y);
            vd[2] = to_tf32(vv.z); vd[3] = to_tf32(vv.w);
        }
        __syncthreads();

        float sc[8][4];
#pragma unroll
        for (int nt = 0; nt < 8; nt++)
#pragma unroll
            for (int r = 0; r < 4; r++) sc[nt][r] = 0.f;

#pragma unroll
        for (int kk = 0; kk < 64; kk += 8) {
            const int mr = w * 16 + grp;
            uint32_t a0 = Qs[(mr    ) * QK_PAD + kk + tig    ];
            uint32_t a1 = Qs[(mr + 8) * QK_PAD + kk + tig    ];
            uint32_t a2 = Qs[(mr    ) * QK_PAD + kk + tig + 4];
            uint32_t a3 = Qs[(mr + 8) * QK_PAD + kk + tig + 4];
#pragma unroll
            for (int nt = 0; nt < 8; nt++) {
                uint32_t b0 = Ks[(nt * 8 + grp) * QK_PAD + kk + tig    ];
                uint32_t b1 = Ks[(nt * 8 + grp) * QK_PAD + kk + tig + 4];
                mma_tf32(sc[nt], a0, a1, a2, a3, b0, b1);
            }
        }

        const bool diag = (kt == qt);
        float mx0 = -3.0e38f, mx1 = -3.0e38f;
#pragma unroll
        for (int nt = 0; nt < 8; nt++) {
            int cg = kt * 64 + nt * 8 + 2 * tig;
            float s0 = sc[nt][0] * frs0;
            float s1 = sc[nt][1] * frs0;
            float s2 = sc[nt][2] * frs1;
            float s3 = sc[nt][3] * frs1;
            if (diag) {
                if (cg     >= rg0)     s0 = -1e30f;
                if (cg + 1 >= rg0)     s1 = -1e30f;
                if (cg     >= rg0 + 8) s2 = -1e30f;
                if (cg + 1 >= rg0 + 8) s3 = -1e30f;
            }
            sc[nt][0] = s0; sc[nt][1] = s1; sc[nt][2] = s2; sc[nt][3] = s3;
            mx0 = fmaxf(mx0, fmaxf(s0, s1));
            mx1 = fmaxf(mx1, fmaxf(s2, s3));
        }
        mx0 = fmaxf(mx0, __shfl_xor_sync(0xffffffffu, mx0, 1));
        mx0 = fmaxf(mx0, __shfl_xor_sync(0xffffffffu, mx0, 2));
        mx1 = fmaxf(mx1, __shfl_xor_sync(0xffffffffu, mx1, 1));
        mx1 = fmaxf(mx1, __shfl_xor_sync(0xffffffffu, mx1, 2));

        float mn0 = fmaxf(m0, mx0);
        float mn1 = fmaxf(m1, mx1);
        float al0 = __expf(m0 - mn0);
        float al1 = __expf(m1 - mn1);
        m0 = mn0; m1 = mn1;

        float su0 = 0.f, su1 = 0.f;
        uint32_t pu[8][4];
#pragma unroll
        for (int nt = 0; nt < 8; nt++) {
            float p0 = __expf(sc[nt][0] - mn0);
            float p1 = __expf(sc[nt][1] - mn0);
            float p2 = __expf(sc[nt][2] - mn1);
            float p3 = __expf(sc[nt][3] - mn1);
            su0 += p0 + p1;
            su1 += p2 + p3;
            pu[nt][0] = to_tf32(p0); pu[nt][1] = to_tf32(p1);
            pu[nt][2] = to_tf32(p2); pu[nt][3] = to_tf32(p3);
        }
        su0 += __shfl_xor_sync(0xffffffffu, su0, 1);
        su0 += __shfl_xor_sync(0xffffffffu, su0, 2);
        su1 += __shfl_xor_sync(0xffffffffu, su1, 1);
        su1 += __shfl_xor_sync(0xffffffffu, su1, 2);
        l0 = l0 * al0 + su0;
        l1 = l1 * al1 + su1;
#pragma unroll
        for (int nt = 0; nt < 8; nt++) {
            o[nt][0] *= al0; o[nt][1] *= al0;
            o[nt][2] *= al1; o[nt][3] *= al1;
        }

        const int srcbase = (lane & ~3) | (tig >> 1);
        const int odd = tig & 1;
#pragma unroll
        for (int j = 0; j < 8; j++) {
            uint32_t x0a = __shfl_sync(0xffffffffu, pu[j][0], srcbase);
            uint32_t x1a = __shfl_sync(0xffffffffu, pu[j][1], srcbase);
            uint32_t x2a = __shfl_sync(0xffffffffu, pu[j][2], srcbase);
            uint32_t x3a = __shfl_sync(0xffffffffu, pu[j][3], srcbase);
            uint32_t x0b = __shfl_sync(0xffffffffu, pu[j][0], srcbase + 2);
            uint32_t x1b = __shfl_sync(0xffffffffu, pu[j][1], srcbase + 2);
            uint32_t x2b = __shfl_sync(0xffffffffu, pu[j][2], srcbase + 2);
            uint32_t x3b = __shfl_sync(0xffffffffu, pu[j][3], srcbase + 2);
            uint32_t a0 = odd ? x1a : x0a;
            uint32_t a1 = odd ? x3a : x2a;
            uint32_t a2 = odd ? x1b : x0b;
            uint32_t a3 = odd ? x3b : x2b;
#pragma unroll
            for (int nt = 0; nt < 8; nt++) {
                uint32_t b0 = Vs[(j * 8 + tig    ) * V_PAD + nt * 8 + grp];
                uint32_t b1 = Vs[(j * 8 + tig + 4) * V_PAD + nt * 8 + grp];
                mma_tf32(o[nt], a0, a1, a2, a3, b0, b1);
            }
        }
    }

    float inv0 = (rg0 == 0) ? 0.f : (1.0f / l0);
    float inv1 = 1.0f / l1;
#pragma unroll
    for (int nt = 0; nt < 8; nt++) {
        int col = nt * 8 + tig * 2;
        *(__half2*)(AH + base + (size_t)(rg0    ) * DD + col) =
            __floats2half2_rn(o[nt][0] * inv0, o[nt][1] * inv0);
        *(__half2*)(AH + base + (size_t)(rg0 + 8) * DD + col) =
            __floats2half2_rn(o[nt][2] * inv1, o[nt][3] * inv1);
    }
}

// ---------------------------------------------------------------------------
// out = LayerNorm(x + r)*g + be; optional fp16 copy outh
// ---------------------------------------------------------------------------
__global__ void __launch_bounds__(128) ln_res_kernel(
    const float* __restrict__ x, const float* __restrict__ r,
    const float* __restrict__ g, const float* __restrict__ be,
    float* __restrict__ out, __half* __restrict__ outh)
{
    int row = blockIdx.x;
    int tid = threadIdx.x;
    const float4* xp = (const float4*)(x + (size_t)row * DD);
    const float4* rp = (const float4*)(r + (size_t)row * DD);
    float4 v = xp[tid], w = rp[tid];
    v.x += w.x; v.y += w.y; v.z += w.z; v.w += w.w;
    float s  = v.x + v.y + v.z + v.w;
    float ss = v.x * v.x + v.y * v.y + v.z * v.z + v.w * v.w;
#pragma unroll
    for (int ofs = 16; ofs > 0; ofs >>= 1) {
        s  += __shfl_xor_sync(0xffffffffu, s,  ofs);
        ss += __shfl_xor_sync(0xffffffffu, ss, ofs);
    }
    __shared__ float sb[4], ssb[4];
    int wid = tid >> 5;
    if ((tid & 31) == 0) { sb[wid] = s; ssb[wid] = ss; }
    __syncthreads();
    s  = sb[0]  + sb[1]  + sb[2]  + sb[3];
    ss = ssb[0] + ssb[1] + ssb[2] + ssb[3];
    float mean = s * (1.0f / DD);
    float var  = ss * (1.0f / DD) - mean * mean;
    float rs   = rsqrtf(var + 1e-5f);
    float4 gv = ((const float4*)g)[tid];
    float4 bv = ((const float4*)be)[tid];
    float4 o4;
    o4.x = (v.x - mean) * rs * gv.x + bv.x;
    o4.y = (v.y - mean) * rs * gv.y + bv.y;
    o4.z = (v.z - mean) * rs * gv.z + bv.z;
    o4.w = (v.w - mean) * rs * gv.w + bv.w;
    ((float4*)(out + (size_t)row * DD))[tid] = o4;
    if (outh) {
        size_t e = (size_t)row * DD + tid * 4;
        ((__half2*)(outh + e))[0] = __floats2half2_rn(o4.x, o4.y);
        ((__half2*)(outh + e))[1] = __floats2half2_rn(o4.z, o4.w);
    }
}

// ---------------------------------------------------------------------------
extern "C" void kernel_launch(void* const* d_in, const int* in_sizes, int n_in,
                              void* d_out, int out_size)
{
    const float* qe  = (const float*)d_in[0];
    const float* qa  = (const float*)d_in[1];
    const float* fr  = (const float*)d_in[2];
    const float* pe  = (const float*)d_in[3];
    const float* Wk  = (const float*)d_in[4];
    const float* bk  = (const float*)d_in[5];
    const float* Wv  = (const float*)d_in[6];
    const float* bv  = (const float*)d_in[7];
    const float* Wo  = (const float*)d_in[8];
    const float* bo  = (const float*)d_in[9];
    const float* g1  = (const float*)d_in[10];
    const float* be1 = (const float*)d_in[11];
    const float* W1  = (const float*)d_in[12];
    const float* bf1 = (const float*)d_in[13];
    const float* W2  = (const float*)d_in[14];
    const float* bf2 = (const float*)d_in[15];
    const float* g2  = (const float*)d_in[16];
    const float* be2 = (const float*)d_in[17];
    float* out = (float*)d_out;

    float  *px, *pq, *pv, *pt;
    __half *pxh, *pyh, *pah, *pfh, *pwkt, *pwvt, *pwot, *pw1t, *pw2t;
    cudaGetSymbolAddress((void**)&px,   g_x);
    cudaGetSymbolAddress((void**)&pq,   g_q);
    cudaGetSymbolAddress((void**)&pv,   g_v);
    cudaGetSymbolAddress((void**)&pt,   g_t);
    cudaGetSymbolAddress((void**)&pxh,  g_xh);
    cudaGetSymbolAddress((void**)&pyh,  g_yh);
    cudaGetSymbolAddress((void**)&pah,  g_ah);
    cudaGetSymbolAddress((void**)&pfh,  g_fh);
    cudaGetSymbolAddress((void**)&pwkt, g_wkt);
    cudaGetSymbolAddress((void**)&pwvt, g_wvt);
    cudaGetSymbolAddress((void**)&pwot, g_wot);
    cudaGetSymbolAddress((void**)&pw1t, g_w1t);
    cudaGetSymbolAddress((void**)&pw2t, g_w2t);

    cudaFuncSetAttribute(attn_mma_kernel,
                         cudaFuncAttributeMaxDynamicSharedMemorySize, (int)ATTN_SMEM);
    cudaFuncSetAttribute(f16_gemm<0>,
                         cudaFuncAttributeMaxDynamicSharedMemorySize, (int)GEMM_SMEM);
    cudaFuncSetAttribute(f16_gemm<1>,
                         cudaFuncAttributeMaxDynamicSharedMemorySize, (int)GEMM_SMEM);

    // one-shot weight transpose + fp16 convert (all 10 matrices)
    wtrans_all_kernel<<<dim3(64, 64, 10), dim3(32, 8)>>>(
        Wk, Wv, Wo, W1, W2, pwkt, pwvt, pwot, pw1t, pw2t);

    add_pe_kernel<<<(BSD / 4 + 255) / 256, 256>>>(
        (const float4*)qe, (const float4*)qa, (const float4*)pe,
        (float4*)px, pxh, pyh);

    dim3 g512 (DD / 128, MTOK / 128, 1);   // (4, 128)
    dim3 g512z(DD / 128, MTOK / 128, 2);   // merged q & v
    dim3 gff  (FFD / 128, MTOK / 128, 1);  // (16, 128)
    dim3 gattn(SS / 64, BB * HH);          // (8, 256)

    for (int i = 0; i < NBLK; i++) {
        const __half* wkt = pwkt + (size_t)i * DD * DD;
        const __half* wvt = pwvt + (size_t)i * DD * DD;
        const __half* wot = pwot + (size_t)i * DD * DD;
        const __half* w1t = pw1t + (size_t)i * DD * FFD;
        const __half* w2t = pw2t + (size_t)i * FFD * DD;

        // merged: z=0 -> q = x@Wk + bk (fp32) ; z=1 -> v = y@Wv + bv (fp32)
        f16_gemm<0><<<g512z, 256, GEMM_SMEM>>>(
            pxh, wkt, bk + i * DD, pq,
            pyh, wvt, bv + i * DD, pv, MTOK, DD, DD);
        // attention -> fp16 ah
        attn_mma_kernel<<<gattn, 128, ATTN_SMEM>>>(pq, pv, fr, pah);
        // proj = ah @ Wo + bo -> pt (fp32)
        f16_gemm<0><<<g512, 256, GEMM_SMEM>>>(
            pah, wot, bo + i * DD, pt,
            pah, wot, bo + i * DD, pt, MTOK, DD, DD);
        // x = LN(x + proj); xh = fp16(x)
        ln_res_kernel<<<MTOK, 128>>>(px, pt, g1 + i * DD, be1 + i * DD, px, pxh);
        // hidden = relu(x @ W1 + bf1) -> fp16 fh
        f16_gemm<1><<<gff, 256, GEMM_SMEM>>>(
            pxh, w1t, bf1 + i * FFD, pfh,
            pxh, w1t, bf1 + i * FFD, pfh, MTOK, FFD, DD);
        // ffn = fh @ W2 + bf2 -> pt (fp32)
        f16_gemm<0><<<g512, 256, GEMM_SMEM>>>(
            pfh, w2t, bf2 + i * DD, pt,
            pfh, w2t, bf2 + i * DD, pt, MTOK, DD, FFD);
        // x = LN(x + ffn)
        float*  dst = (i == NBLK - 1) ? out : px;
        __half* dh  = (i == NBLK - 1) ? nullptr : pxh;
        ln_res_kernel<<<MTOK, 128>>>(px, pt, g2 + i * DD, be2 + i * DD, dst, dh);
    }
}

// round 11
// speedup vs baseline: 2.2112x; 1.0737x over previous
#include <cuda_runtime.h>
#include <cuda_fp16.h>
#include <math.h>
#include <stdint.h>

// Problem constants
#define BB   32
#define SS   512
#define DD   512
#define HH   8
#define DKK  64
#define FFD  2048
#define NBLK 2
#define MTOK (BB*SS)            // 16384 token rows
#define BSD  (BB*SS*DD)         // 8388608
#define BSF  (BB*SS*FFD)        // 33554432

// Scratch (static device globals — no allocation allowed)
__device__ float  g_x[BSD];          // residual stream (fp32)
__device__ float  g_t[BSD];          // fp32 temp (proj / ffn out)
__device__ __half g_qh[BSD];         // q (fp16, attn input)
__device__ __half g_vh[BSD];         // v (fp16, attn input)
__device__ __half g_xh[BSD];         // fp16 activations
__device__ __half g_yh[BSD];
__device__ __half g_ah[BSD];         // attn output (fp16)
__device__ __half g_fh[BSF];         // ffn hidden (fp16)
__device__ __half g_wkt[NBLK*DD*DD]; // transposed fp16 weights [N][K]
__device__ __half g_wvt[NBLK*DD*DD];
__device__ __half g_wot[NBLK*DD*DD];
__device__ __half g_w1t[NBLK*DD*FFD];
__device__ __half g_w2t[NBLK*FFD*DD];

// ---------------------------------------------------------------------------
// helpers
// ---------------------------------------------------------------------------
__device__ __forceinline__ void mma_f16(float c[4],
                                        uint32_t a0, uint32_t a1,
                                        uint32_t a2, uint32_t a3,
                                        uint32_t b0, uint32_t b1)
{
    asm volatile(
        "mma.sync.aligned.m16n8k16.row.col.f32.f16.f16.f32 "
        "{%0,%1,%2,%3}, {%4,%5,%6,%7}, {%8,%9}, {%0,%1,%2,%3};"
        : "+f"(c[0]), "+f"(c[1]), "+f"(c[2]), "+f"(c[3])
        : "r"(a0), "r"(a1), "r"(a2), "r"(a3), "r"(b0), "r"(b1));
}
__device__ __forceinline__ void cp_async16(uint32_t smem_addr, const void* gptr) {
    asm volatile("cp.async.cg.shared.global [%0], [%1], 16;"
                 :: "r"(smem_addr), "l"(gptr));
}
__device__ __forceinline__ void cp_commit() {
    asm volatile("cp.async.commit_group;");
}
template<int N>
__device__ __forceinline__ void cp_wait() {
    asm volatile("cp.async.wait_group %0;" :: "n"(N));
}
__device__ __forceinline__ uint32_t pack_h2(__half lo, __half hi) {
    __half2 h; h.x = lo; h.y = hi;
    return *(uint32_t*)&h;
}
__device__ __forceinline__ uint32_t h2u(__half2 h) {
    return *(uint32_t*)&h;
}

// ---------------------------------------------------------------------------
// One-shot weight transpose + fp16 convert for ALL weights.
// W[K][N] fp32 -> Wt[N][K] fp16.  z in [0,10): (matrix, block) pairs.
// ---------------------------------------------------------------------------
__global__ void wtrans_all_kernel(
    const float* __restrict__ Wk, const float* __restrict__ Wv,
    const float* __restrict__ Wo, const float* __restrict__ W1,
    const float* __restrict__ W2,
    __half* __restrict__ twk, __half* __restrict__ twv,
    __half* __restrict__ two, __half* __restrict__ tw1,
    __half* __restrict__ tw2)
{
    const int z   = blockIdx.z;
    const int blk = z & 1;
    const float* W; __half* T; int K, N;
    switch (z >> 1) {
        case 0: W = Wk + (size_t)blk * DD * DD;  T = twk + (size_t)blk * DD * DD;  K = DD;  N = DD;  break;
        case 1: W = Wv + (size_t)blk * DD * DD;  T = twv + (size_t)blk * DD * DD;  K = DD;  N = DD;  break;
        case 2: W = Wo + (size_t)blk * DD * DD;  T = two + (size_t)blk * DD * DD;  K = DD;  N = DD;  break;
        case 3: W = W1 + (size_t)blk * DD * FFD; T = tw1 + (size_t)blk * DD * FFD; K = DD;  N = FFD; break;
        default:W = W2 + (size_t)blk * FFD * DD; T = tw2 + (size_t)blk * FFD * DD; K = FFD; N = DD;  break;
    }
    const int n0 = blockIdx.x * 32;
    const int k0 = blockIdx.y * 32;
    if (n0 >= N || k0 >= K) return;

    __shared__ float t[32][33];
    const int tx = threadIdx.x, ty = threadIdx.y;
    for (int j = ty; j < 32; j += 8)
        t[j][tx] = W[(size_t)(k0 + j) * N + n0 + tx];
    __syncthreads();
    for (int j = ty; j < 32; j += 8)
        T[(size_t)(n0 + j) * K + k0 + tx] = __float2half_rn(t[tx][j]);
}

// ---------------------------------------------------------------------------
// x = qe+pe (fp32 residual) + fp16 copies xh, yh of both streams
// ---------------------------------------------------------------------------
__global__ void add_pe_kernel(const float4* __restrict__ qe,
                              const float4* __restrict__ qa,
                              const float4* __restrict__ pe,
                              float4* __restrict__ x,
                              __half* __restrict__ xh, __half* __restrict__ yh)
{
    int i = blockIdx.x * blockDim.x + threadIdx.x;
    const int n4 = BSD / 4;
    if (i >= n4) return;
    int pi = i & (SS * DD / 4 - 1);
    float4 p = pe[pi];
    float4 a = qe[i];
    a.x += p.x; a.y += p.y; a.z += p.z; a.w += p.w;
    x[i] = a;
    ((__half2*)(xh + 4 * (size_t)i))[0] = __floats2half2_rn(a.x, a.y);
    ((__half2*)(xh + 4 * (size_t)i))[1] = __floats2half2_rn(a.z, a.w);
    float4 b = qa[i];
    b.x += p.x; b.y += p.y; b.z += p.z; b.w += p.w;
    ((__half2*)(yh + 4 * (size_t)i))[0] = __floats2half2_rn(b.x, b.y);
    ((__half2*)(yh + 4 * (size_t)i))[1] = __floats2half2_rn(b.z, b.w);
}

// ---------------------------------------------------------------------------
// FP16 tensor-core GEMM: C[M,N] = A[M,K] @ Wt[N,K]^T + bias[N]
// MODE 0: fp32 out. MODE 1: ReLU + fp16 out. MODE 2: fp16 out.
// ---------------------------------------------------------------------------
#define HST 40
#define HTILE (128 * HST)
#define STGH (2 * HTILE)
#define NSTG 3
#define GEMM_SMEM (NSTG * STGH * sizeof(__half))   // 61440 B

template<int MODE>
__global__ void __launch_bounds__(256, 2) f16_gemm(
    const __half* __restrict__ A0, const __half* __restrict__ W0,
    const float* __restrict__ b0p, void* __restrict__ C0,
    const __half* __restrict__ A1, const __half* __restrict__ W1p,
    const float* __restrict__ b1p, void* __restrict__ C1,
    int M, int N, int K)
{
    extern __shared__ __half smh[];

    const __half* A    = blockIdx.z ? A1  : A0;
    const __half* W    = blockIdx.z ? W1p : W0;
    const float*  bias = blockIdx.z ? b1p : b0p;
    void*         C    = blockIdx.z ? C1  : C0;

    const int tid  = threadIdx.x;
    const int lane = tid & 31;
    const int wid  = tid >> 5;
    const int wm   = wid & 1;
    const int wn   = wid >> 1;
    const int grp  = lane >> 2;
    const int tig  = lane & 3;
    const int m0   = blockIdx.y * 128;
    const int n0   = blockIdx.x * 128;

    const uint32_t sS = (uint32_t)__cvta_generic_to_shared(smh);

    const int l_row = tid >> 1;
    const int l_h0  = (tid & 1) * 16;

    float acc[4][4][4];
#pragma unroll
    for (int i = 0; i < 4; i++)
#pragma unroll
        for (int j = 0; j < 4; j++)
#pragma unroll
            for (int r = 0; r < 4; r++) acc[i][j][r] = 0.f;

    const int nk = K >> 5;

    auto load_stage = [&](int stg, int k0) {
        const uint32_t sb = sS + (uint32_t)(stg * STGH * 2);
        {
            const __half* ga = A + (size_t)(m0 + l_row) * K + k0 + l_h0;
            uint32_t da = sb + (uint32_t)((l_row * HST + l_h0) * 2);
            cp_async16(da,      ga);
            cp_async16(da + 16, ga + 8);
        }
        {
            const __half* gb = W + (size_t)(n0 + l_row) * K + k0 + l_h0;
            uint32_t db = sb + (uint32_t)((HTILE + l_row * HST + l_h0) * 2);
            cp_async16(db,      gb);
            cp_async16(db + 16, gb + 8);
        }
    };

    load_stage(0, 0);
    cp_commit();
    load_stage(1, 32);
    cp_commit();

    for (int kt = 0; kt < nk; kt++) {
        if (kt + NSTG - 1 < nk) {
            int s = kt + NSTG - 1;
            load_stage(s % NSTG, s * 32);
        }
        cp_commit();
        cp_wait<NSTG - 1>();
        __syncthreads();

        const __half* pA = smh + (kt % NSTG) * STGH;
        const __half* pB = pA + HTILE;

#pragma unroll
        for (int kk = 0; kk < 32; kk += 16) {
            uint32_t af[4][4];
            uint32_t bf[4][2];
#pragma unroll
            for (int mt = 0; mt < 4; mt++) {
                int mr = wm * 64 + mt * 16 + grp;
                af[mt][0] = *(const uint32_t*)(pA + (mr    ) * HST + kk + 2 * tig    );
                af[mt][1] = *(const uint32_t*)(pA + (mr + 8) * HST + kk + 2 * tig    );
                af[mt][2] = *(const uint32_t*)(pA + (mr    ) * HST + kk + 2 * tig + 8);
                af[mt][3] = *(const uint32_t*)(pA + (mr + 8) * HST + kk + 2 * tig + 8);
            }
#pragma unroll
            for (int nt = 0; nt < 4; nt++) {
                int nc = wn * 32 + nt * 8 + grp;
                bf[nt][0] = *(const uint32_t*)(pB + nc * HST + kk + 2 * tig    );
                bf[nt][1] = *(const uint32_t*)(pB + nc * HST + kk + 2 * tig + 8);
            }
#pragma unroll
            for (int mt = 0; mt < 4; mt++)
#pragma unroll
                for (int nt = 0; nt < 4; nt++)
                    mma_f16(acc[mt][nt],
                            af[mt][0], af[mt][1], af[mt][2], af[mt][3],
                            bf[nt][0], bf[nt][1]);
        }
        __syncthreads();
    }

#pragma unroll
    for (int mt = 0; mt < 4; mt++) {
#pragma unroll
        for (int nt = 0; nt < 4; nt++) {
            int row = m0 + wm * 64 + mt * 16 + grp;
            int col = n0 + wn * 32 + nt * 8 + tig * 2;
            float bb0 = bias[col], bb1 = bias[col + 1];
            float v0 = acc[mt][nt][0] + bb0;
            float v1 = acc[mt][nt][1] + bb1;
            float v2 = acc[mt][nt][2] + bb0;
            float v3 = acc[mt][nt][3] + bb1;
            if (MODE == 0) {
                float* Cf = (float*)C;
                *(float2*)(Cf + (size_t)row * N + col)       = make_float2(v0, v1);
                *(float2*)(Cf + (size_t)(row + 8) * N + col) = make_float2(v2, v3);
            } else {
                if (MODE == 1) {
                    v0 = fmaxf(v0, 0.f); v1 = fmaxf(v1, 0.f);
                    v2 = fmaxf(v2, 0.f); v3 = fmaxf(v3, 0.f);
                }
                __half* Ch = (__half*)C;
                *(__half2*)(Ch + (size_t)row * N + col)       = __floats2half2_rn(v0, v1);
                *(__half2*)(Ch + (size_t)(row + 8) * N + col) = __floats2half2_rn(v2, v3);
            }
        }
    }
}

// ---------------------------------------------------------------------------
// FP16 tensor-core flash attention. Q,V fp16 in; fp16 out.
// m16n8k16 mma; P fragment = packed S accumulator (no shuffles).
// Smem: Qs/Ks/Vs [64][72] halves (27648 B dynamic).
// ---------------------------------------------------------------------------
#define APADH 72
#define ATTN_SMEM (3 * 64 * APADH * sizeof(__half))

__global__ void __launch_bounds__(128, 4) attn_f16_kernel(
    const __half* __restrict__ Q, const __half* __restrict__ V,
    const float* __restrict__ FR, __half* __restrict__ AH)
{
    extern __shared__ __half smh[];
    __half* Qs = smh;                    // [64][APADH]
    __half* Ks = smh + 64 * APADH;
    __half* Vs = smh + 2 * 64 * APADH;   // [key][dk]

    const int qt   = gridDim.x - 1 - blockIdx.x;   // heavy-first
    const int bh   = blockIdx.y;
    const int b    = bh >> 3;
    const int h    = bh & 7;
    const int tid  = threadIdx.x;
    const int lane = tid & 31;
    const int w    = tid >> 5;
    const int grp  = lane >> 2;
    const int tig  = lane & 3;
    const int q0   = qt * 64;
    const size_t base = (size_t)b * SS * DD + (size_t)h * DKK;

    // load Q tile (64 rows x 64 halves; 512 chunks of 8 halves)
#pragma unroll
    for (int j = 0; j < 4; j++) {
        int idx = j * 128 + tid;
        int r   = idx >> 3;
        int c8  = (idx & 7) * 8;
        *(float4*)(Qs + r * APADH + c8) =
            *(const float4*)(Q + base + (size_t)(q0 + r) * DD + c8);
    }

    const int rg0 = q0 + w * 16 + grp;
    const float frs0 = FR[b * SS + rg0]     * 0.125f;
    const float frs1 = FR[b * SS + rg0 + 8] * 0.125f;

    float m0 = -3.0e38f, m1 = -3.0e38f, l0 = 0.f, l1 = 0.f;
    float o[8][4];
#pragma unroll
    for (int nt = 0; nt < 8; nt++)
#pragma unroll
        for (int r = 0; r < 4; r++) o[nt][r] = 0.f;

    for (int kt = 0; kt <= qt; kt++) {
        __syncthreads();
#pragma unroll
        for (int j = 0; j < 4; j++) {
            int idx = j * 128 + tid;
            int r   = idx >> 3;
            int c8  = (idx & 7) * 8;
            *(float4*)(Ks + r * APADH + c8) =
                *(const float4*)(Q + base + (size_t)(kt * 64 + r) * DD + c8);
            *(float4*)(Vs + r * APADH + c8) =
                *(const float4*)(V + base + (size_t)(kt * 64 + r) * DD + c8);
        }
        __syncthreads();

        // --- S = Q K^T (16 rows x 64 keys), fp16 k16 ---
        float sc[8][4];
#pragma unroll
        for (int nt = 0; nt < 8; nt++)
#pragma unroll
            for (int r = 0; r < 4; r++) sc[nt][r] = 0.f;

        const int mr = w * 16 + grp;
#pragma unroll
        for (int kc = 0; kc < 4; kc++) {
            const int k0 = kc * 16;
            uint32_t a0 = *(const uint32_t*)(Qs + (mr    ) * APADH + k0 + 2 * tig    );
            uint32_t a1 = *(const uint32_t*)(Qs + (mr + 8) * APADH + k0 + 2 * tig    );
            uint32_t a2 = *(const uint32_t*)(Qs + (mr    ) * APADH + k0 + 2 * tig + 8);
            uint32_t a3 = *(const uint32_t*)(Qs + (mr + 8) * APADH + k0 + 2 * tig + 8);
#pragma unroll
            for (int nt = 0; nt < 8; nt++) {
                int nc = nt * 8 + grp;
                uint32_t b0 = *(const uint32_t*)(Ks + nc * APADH + k0 + 2 * tig    );
                uint32_t b1 = *(const uint32_t*)(Ks + nc * APADH + k0 + 2 * tig + 8);
                mma_f16(sc[nt], a0, a1, a2, a3, b0, b1);
            }
        }

        // --- scale + mask + online softmax ---
        const bool diag = (kt == qt);
        float mx0 = -3.0e38f, mx1 = -3.0e38f;
#pragma unroll
        for (int nt = 0; nt < 8; nt++) {
            int cg = kt * 64 + nt * 8 + 2 * tig;
            float s0 = sc[nt][0] * frs0;
            float s1 = sc[nt][1] * frs0;
            float s2 = sc[nt][2] * frs1;
            float s3 = sc[nt][3] * frs1;
            if (diag) {
                if (cg     >= rg0)     s0 = -1e30f;
                if (cg + 1 >= rg0)     s1 = -1e30f;
                if (cg     >= rg0 + 8) s2 = -1e30f;
                if (cg + 1 >= rg0 + 8) s3 = -1e30f;
            }
            sc[nt][0] = s0; sc[nt][1] = s1; sc[nt][2] = s2; sc[nt][3] = s3;
            mx0 = fmaxf(mx0, fmaxf(s0, s1));
            mx1 = fmaxf(mx1, fmaxf(s2, s3));
        }
        mx0 = fmaxf(mx0, __shfl_xor_sync(0xffffffffu, mx0, 1));
        mx0 = fmaxf(mx0, __shfl_xor_sync(0xffffffffu, mx0, 2));
        mx1 = fmaxf(mx1, __shfl_xor_sync(0xffffffffu, mx1, 1));
        mx1 = fmaxf(mx1, __shfl_xor_sync(0xffffffffu, mx1, 2));

        float mn0 = fmaxf(m0, mx0);
        float mn1 = fmaxf(m1, mx1);
        float al0 = __expf(m0 - mn0);
        float al1 = __expf(m1 - mn1);
        m0 = mn0; m1 = mn1;

        float su0 = 0.f, su1 = 0.f;
        uint32_t pu[8][2];   // packed P: [0]=(row grp, 2 cols), [1]=(row grp+8)
#pragma unroll
        for (int nt = 0; nt < 8; nt++) {
            float p0 = __expf(sc[nt][0] - mn0);
            float p1 = __expf(sc[nt][1] - mn0);
            float p2 = __expf(sc[nt][2] - mn1);
            float p3 = __expf(sc[nt][3] - mn1);
            su0 += p0 + p1;
            su1 += p2 + p3;
            pu[nt][0] = h2u(__floats2half2_rn(p0, p1));
            pu[nt][1] = h2u(__floats2half2_rn(p2, p3));
        }
        su0 += __shfl_xor_sync(0xffffffffu, su0, 1);
        su0 += __shfl_xor_sync(0xffffffffu, su0, 2);
        su1 += __shfl_xor_sync(0xffffffffu, su1, 1);
        su1 += __shfl_xor_sync(0xffffffffu, su1, 2);
        l0 = l0 * al0 + su0;
        l1 = l1 * al1 + su1;
#pragma unroll
        for (int nt = 0; nt < 8; nt++) {
            o[nt][0] *= al0; o[nt][1] *= al0;
            o[nt][2] *= al1; o[nt][3] *= al1;
        }

        // --- O += P V : A-frag = packed C-frag, B via 2x u16 loads ---
#pragma unroll
        for (int j = 0; j < 4; j++) {
            const int k0 = j * 16;
            uint32_t a0 = pu[2 * j    ][0];
            uint32_t a1 = pu[2 * j    ][1];
            uint32_t a2 = pu[2 * j + 1][0];
            uint32_t a3 = pu[2 * j + 1][1];
#pragma unroll
            for (int nt = 0; nt < 8; nt++) {
                int n = nt * 8 + grp;
                uint32_t b0 = pack_h2(Vs[(k0 + 2 * tig    ) * APADH + n],
                                      Vs[(k0 + 2 * tig + 1) * APADH + n]);
                uint32_t b1 = pack_h2(Vs[(k0 + 2 * tig + 8) * APADH + n],
                                      Vs[(k0 + 2 * tig + 9) * APADH + n]);
                mma_f16(o[nt], a0, a1, a2, a3, b0, b1);
            }
        }
    }

    float inv0 = (rg0 == 0) ? 0.f : (1.0f / l0);
    float inv1 = 1.0f / l1;
#pragma unroll
    for (int nt = 0; nt < 8; nt++) {
        int col = nt * 8 + tig * 2;
        *(__half2*)(AH + base + (size_t)(rg0    ) * DD + col) =
            __floats2half2_rn(o[nt][0] * inv0, o[nt][1] * inv0);
        *(__half2*)(AH + base + (size_t)(rg0 + 8) * DD + col) =
            __floats2half2_rn(o[nt][2] * inv1, o[nt][3] * inv1);
    }
}

// ---------------------------------------------------------------------------
// out = LayerNorm(x + r)*g + be; optional fp16 copy outh
// ---------------------------------------------------------------------------
__global__ void __launch_bounds__(128) ln_res_kernel(
    const float* __restrict__ x, const float* __restrict__ r,
    const float* __restrict__ g, const float* __restrict__ be,
    float* __restrict__ out, __half* __restrict__ outh)
{
    int row = blockIdx.x;
    int tid = threadIdx.x;
    const float4* xp = (const float4*)(x + (size_t)row * DD);
    const float4* rp = (const float4*)(r + (size_t)row * DD);
    float4 v = xp[tid], w = rp[tid];
    v.x += w.x; v.y += w.y; v.z += w.z; v.w += w.w;
    float s  = v.x + v.y + v.z + v.w;
    float ss = v.x * v.x + v.y * v.y + v.z * v.z + v.w * v.w;
#pragma unroll
    for (int ofs = 16; ofs > 0; ofs >>= 1) {
        s  += __shfl_xor_sync(0xffffffffu, s,  ofs);
        ss += __shfl_xor_sync(0xffffffffu, ss, ofs);
    }
    __shared__ float sb[4], ssb[4];
    int wid = tid >> 5;
    if ((tid & 31) == 0) { sb[wid] = s; ssb[wid] = ss; }
    __syncthreads();
    s  = sb[0]  + sb[1]  + sb[2]  + sb[3];
    ss = ssb[0] + ssb[1] + ssb[2] + ssb[3];
    float mean = s * (1.0f / DD);
    float var  = ss * (1.0f / DD) - mean * mean;
    float rs   = rsqrtf(var + 1e-5f);
    float4 gv = ((const float4*)g)[tid];
    float4 bv = ((const float4*)be)[tid];
    float4 o4;
    o4.x = (v.x - mean) * rs * gv.x + bv.x;
    o4.y = (v.y - mean) * rs * gv.y + bv.y;
    o4.z = (v.z - mean) * rs * gv.z + bv.z;
    o4.w = (v.w - mean) * rs * gv.w + bv.w;
    ((float4*)(out + (size_t)row * DD))[tid] = o4;
    if (outh) {
        size_t e = (size_t)row * DD + tid * 4;
        ((__half2*)(outh + e))[0] = __floats2half2_rn(o4.x, o4.y);
        ((__half2*)(outh + e))[1] = __floats2half2_rn(o4.z, o4.w);
    }
}

// ---------------------------------------------------------------------------
extern "C" void kernel_launch(void* const* d_in, const int* in_sizes, int n_in,
                              void* d_out, int out_size)
{
    const float* qe  = (const float*)d_in[0];
    const float* qa  = (const float*)d_in[1];
    const float* fr  = (const float*)d_in[2];
    const float* pe  = (const float*)d_in[3];
    const float* Wk  = (const float*)d_in[4];
    const float* bk  = (const float*)d_in[5];
    const float* Wv  = (const float*)d_in[6];
    const float* bv  = (const float*)d_in[7];
    const float* Wo  = (const float*)d_in[8];
    const float* bo  = (const float*)d_in[9];
    const float* g1  = (const float*)d_in[10];
    const float* be1 = (const float*)d_in[11];
    const float* W1  = (const float*)d_in[12];
    const float* bf1 = (const float*)d_in[13];
    const float* W2  = (const float*)d_in[14];
    const float* bf2 = (const float*)d_in[15];
    const float* g2  = (const float*)d_in[16];
    const float* be2 = (const float*)d_in[17];
    float* out = (float*)d_out;

    float  *px, *pt;
    __half *pqh, *pvh, *pxh, *pyh, *pah, *pfh, *pwkt, *pwvt, *pwot, *pw1t, *pw2t;
    cudaGetSymbolAddress((void**)&px,   g_x);
    cudaGetSymbolAddress((void**)&pt,   g_t);
    cudaGetSymbolAddress((void**)&pqh,  g_qh);
    cudaGetSymbolAddress((void**)&pvh,  g_vh);
    cudaGetSymbolAddress((void**)&pxh,  g_xh);
    cudaGetSymbolAddress((void**)&pyh,  g_yh);
    cudaGetSymbolAddress((void**)&pah,  g_ah);
    cudaGetSymbolAddress((void**)&pfh,  g_fh);
    cudaGetSymbolAddress((void**)&pwkt, g_wkt);
    cudaGetSymbolAddress((void**)&pwvt, g_wvt);
    cudaGetSymbolAddress((void**)&pwot, g_wot);
    cudaGetSymbolAddress((void**)&pw1t, g_w1t);
    cudaGetSymbolAddress((void**)&pw2t, g_w2t);

    cudaFuncSetAttribute(attn_f16_kernel,
                         cudaFuncAttributeMaxDynamicSharedMemorySize, (int)ATTN_SMEM);
    cudaFuncSetAttribute(f16_gemm<0>,
                         cudaFuncAttributeMaxDynamicSharedMemorySize, (int)GEMM_SMEM);
    cudaFuncSetAttribute(f16_gemm<1>,
                         cudaFuncAttributeMaxDynamicSharedMemorySize, (int)GEMM_SMEM);
    cudaFuncSetAttribute(f16_gemm<2>,
                         cudaFuncAttributeMaxDynamicSharedMemorySize, (int)GEMM_SMEM);

    wtrans_all_kernel<<<dim3(64, 64, 10), dim3(32, 8)>>>(
        Wk, Wv, Wo, W1, W2, pwkt, pwvt, pwot, pw1t, pw2t);

    add_pe_kernel<<<(BSD / 4 + 255) / 256, 256>>>(
        (const float4*)qe, (const float4*)qa, (const float4*)pe,
        (float4*)px, pxh, pyh);

    dim3 g512 (DD / 128, MTOK / 128, 1);   // (4, 128)
    dim3 g512z(DD / 128, MTOK / 128, 2);   // merged q & v
    dim3 gff  (FFD / 128, MTOK / 128, 1);  // (16, 128)
    dim3 gattn(SS / 64, BB * HH);          // (8, 256)

    for (int i = 0; i < NBLK; i++) {
        const __half* wkt = pwkt + (size_t)i * DD * DD;
        const __half* wvt = pwvt + (size_t)i * DD * DD;
        const __half* wot = pwot + (size_t)i * DD * DD;
        const __half* w1t = pw1t + (size_t)i * DD * FFD;
        const __half* w2t = pw2t + (size_t)i * FFD * DD;

        // merged: z=0 -> q = x@Wk + bk (fp16) ; z=1 -> v = y@Wv + bv (fp16)
        f16_gemm<2><<<g512z, 256, GEMM_SMEM>>>(
            pxh, wkt, bk + i * DD, pqh,
            pyh, wvt, bv + i * DD, pvh, MTOK, DD, DD);
        // attention (fp16 in/out)
        attn_f16_kernel<<<gattn, 128, ATTN_SMEM>>>(pqh, pvh, fr, pah);
        // proj = ah @ Wo + bo -> pt (fp32)
        f16_gemm<0><<<g512, 256, GEMM_SMEM>>>(
            pah, wot, bo + i * DD, pt,
            pah, wot, bo + i * DD, pt, MTOK, DD, DD);
        // x = LN(x + proj); xh = fp16(x)
        ln_res_kernel<<<MTOK, 128>>>(px, pt, g1 + i * DD, be1 + i * DD, px, pxh);
        // hidden = relu(x @ W1 + bf1) -> fp16 fh
        f16_gemm<1><<<gff, 256, GEMM_SMEM>>>(
            pxh, w1t, bf1 + i * FFD, pfh,
            pxh, w1t, bf1 + i * FFD, pfh, MTOK, FFD, DD);
        // ffn = fh @ W2 + bf2 -> pt (fp32)
        f16_gemm<0><<<g512, 256, GEMM_SMEM>>>(
            pfh, w2t, bf2 + i * DD, pt,
            pfh, w2t, bf2 + i * DD, pt, MTOK, DD, FFD);
        // x = LN(x + ffn)
        float*  dst = (i == NBLK - 1) ? out : px;
        __half* dh  = (i == NBLK - 1) ? nullptr : pxh;
        ln_res_kernel<<<MTOK, 128>>>(px, pt, g2 + i * DD, be2 + i * DD, dst, dh);
    }
}